// round 6
// baseline (speedup 1.0000x reference)
#include <cuda_runtime.h>
#include <cuda_bf16.h>
#include <cstdint>

// ---------------- Problem constants ----------------
#define NROWS   16384
#define QKVW    1536
#define POOLROWS 4064
#define YROWS    8160

// ---------------- Device scratch ----------------
__device__ __align__(16) float g_qkv[(size_t)NROWS * QKVW];
__device__ __align__(16) float g_poolq[(size_t)32 * POOLROWS * 64];
__device__ __align__(16) float g_poolk[(size_t)32 * POOLROWS * 64];
__device__ __align__(16) float g_poolv[(size_t)32 * POOLROWS * 64];
__device__ __align__(16) float g_Y[(size_t)32 * YROWS * 64];
__device__ __align__(16) float g_Asum[(size_t)32 * YROWS];

// bf16 hi/lo planes (GEMM2 only)
__device__ __align__(16) __nv_bfloat16 g_woh[(size_t)1024 * 512];
__device__ __align__(16) __nv_bfloat16 g_wol[(size_t)1024 * 512];
__device__ __align__(16) __nv_bfloat16 g_atth[(size_t)NROWS * 512];
__device__ __align__(16) __nv_bfloat16 g_attl[(size_t)NROWS * 512];

// ---------------- helpers ----------------
__device__ __forceinline__ uint32_t smem_to_u32(const void* p) {
    uint32_t a;
    asm("{ .reg .u64 t; cvta.to.shared.u64 t, %1; cvt.u32.u64 %0, t; }" : "=r"(a) : "l"(p));
    return a;
}
__device__ __forceinline__ uint32_t sw128(uint32_t off) {
    return off ^ ((off >> 3) & 0x70);
}
__device__ __forceinline__ uint32_t f2tf(float f) {
    uint32_t u;
    asm("cvt.rna.tf32.f32 %0, %1;" : "=r"(u) : "f"(f));
    return u;
}

#define LDSM_X4(r0, r1, r2, r3, addr) \
    asm volatile("ldmatrix.sync.aligned.m8n8.x4.shared.b16 {%0,%1,%2,%3}, [%4];" \
        : "=r"(r0), "=r"(r1), "=r"(r2), "=r"(r3) : "r"(addr))

__device__ __forceinline__ void mma16816(float* c, const uint32_t* a, const uint32_t* b) {
    asm volatile(
        "mma.sync.aligned.m16n8k16.row.col.f32.bf16.bf16.f32 "
        "{%0,%1,%2,%3}, {%4,%5,%6,%7}, {%8,%9}, {%0,%1,%2,%3};"
        : "+f"(c[0]), "+f"(c[1]), "+f"(c[2]), "+f"(c[3])
        : "r"(a[0]), "r"(a[1]), "r"(a[2]), "r"(a[3]), "r"(b[0]), "r"(b[1]));
}
__device__ __forceinline__ void mma1688_tf32(float* c, const uint32_t* a, const uint32_t* b) {
    asm volatile(
        "mma.sync.aligned.m16n8k8.row.col.f32.tf32.tf32.f32 "
        "{%0,%1,%2,%3}, {%4,%5,%6,%7}, {%8,%9}, {%0,%1,%2,%3};"
        : "+f"(c[0]), "+f"(c[1]), "+f"(c[2]), "+f"(c[3])
        : "r"(a[0]), "r"(a[1]), "r"(a[2]), "r"(a[3]), "r"(b[0]), "r"(b[1]));
}

__device__ __forceinline__ void split4(float4 v, uint2& hi, uint2& lo) {
    float f[4] = {v.x, v.y, v.z, v.w};
    uint32_t h[4], l[4];
#pragma unroll
    for (int i = 0; i < 4; i++) {
        __nv_bfloat16 hb = __float2bfloat16_rn(f[i]);
        float res = f[i] - __bfloat162float(hb);
        __nv_bfloat16 lb = __float2bfloat16_rn(res);
        h[i] = (uint32_t)__bfloat16_as_ushort(hb);
        l[i] = (uint32_t)__bfloat16_as_ushort(lb);
    }
    hi.x = h[0] | (h[1] << 16); hi.y = h[2] | (h[3] << 16);
    lo.x = l[0] | (l[1] << 16); lo.y = l[2] | (l[3] << 16);
}

// ---------------- convert w_out -> bf16 hi/lo ----------------
__global__ __launch_bounds__(256)
void convert_wout(const float* __restrict__ wo)
{
    int q = blockIdx.x * 256 + threadIdx.x;      // 131072 quads
    float4 v = *(const float4*)(wo + (size_t)q * 4);
    uint2 hi, lo; split4(v, hi, lo);
    ((uint2*)g_woh)[q] = hi;
    ((uint2*)g_wol)[q] = lo;
}

// ---------------- TF32 GEMM: C[M,N] = A[M,K]*B[N,K]^T --------------------
// 128x128 tile, BK=32, 4-stage cp.async. smem rows padded to 36 floats
// (bank-conflict-free frag loads). 8 warps (2m x 4n), warp tile 64x32.
#define T1_STAGE 36864          // A 18432 + B 18432
#define T1_SMEM  (4 * T1_STAGE)

__global__ __launch_bounds__(256, 1)
void gemm_tf32(const float* __restrict__ A, const float* __restrict__ B,
               float* __restrict__ C, int M, int N, int K)
{
    extern __shared__ __align__(1024) char smem[];
    const uint32_t smu = smem_to_u32(smem);
    const int tid = threadIdx.x;
    const int wid = tid >> 5, lane = tid & 31;
    const int warpM = wid & 1, warpN = wid >> 1;     // 2 x 4, warp 64x32
    const int row0 = blockIdx.y * 128;
    const int col0 = blockIdx.x * 128;
    const int KS = K >> 5;

    float acc[4][4][4];
#pragma unroll
    for (int i = 0; i < 4; i++)
#pragma unroll
        for (int j = 0; j < 4; j++)
#pragma unroll
            for (int t = 0; t < 4; t++) acc[i][j][t] = 0.f;

    auto prefetch = [&](int ks, int buf) {
        uint32_t sb = smu + (uint32_t)buf * T1_STAGE;
#pragma unroll
        for (int i = 0; i < 4; i++) {
            int g = tid + (i << 8);
            int r = g >> 3, c4 = g & 7;
            const void* gp = A + (size_t)(row0 + r) * K + ks * 32 + c4 * 4;
            uint32_t sa = sb + r * 144 + c4 * 16;
            asm volatile("cp.async.cg.shared.global [%0], [%1], 16;" :: "r"(sa), "l"(gp));
        }
#pragma unroll
        for (int i = 0; i < 4; i++) {
            int g = tid + (i << 8);
            int r = g >> 3, c4 = g & 7;
            const void* gp = B + (size_t)(col0 + r) * K + ks * 32 + c4 * 4;
            uint32_t sa = sb + 18432 + r * 144 + c4 * 16;
            asm volatile("cp.async.cg.shared.global [%0], [%1], 16;" :: "r"(sa), "l"(gp));
        }
    };

    prefetch(0, 0);
    asm volatile("cp.async.commit_group;" ::: "memory");
    prefetch(1, 1);
    asm volatile("cp.async.commit_group;" ::: "memory");
    prefetch(2, 2);
    asm volatile("cp.async.commit_group;" ::: "memory");

    for (int ks = 0; ks < KS; ks++) {
        asm volatile("cp.async.wait_group 2;" ::: "memory");
        __syncthreads();
        if (ks + 3 < KS) prefetch(ks + 3, (ks + 3) & 3);
        asm volatile("cp.async.commit_group;" ::: "memory");

        const float* As = (const float*)(smem + (ks & 3) * T1_STAGE);
        const float* Bs = As + 4608;
        int lr = lane >> 2, lc = lane & 3;
#pragma unroll
        for (int k8 = 0; k8 < 4; k8++) {
            int kc = k8 * 8 + lc;
            uint32_t bf[4][2];
#pragma unroll
            for (int n8 = 0; n8 < 4; n8++) {
                int cB = warpN * 32 + n8 * 8 + lr;
                bf[n8][0] = f2tf(Bs[cB * 36 + kc]);
                bf[n8][1] = f2tf(Bs[cB * 36 + kc + 4]);
            }
            uint32_t af[4][4];
#pragma unroll
            for (int mt = 0; mt < 4; mt++) {
                int rA = warpM * 64 + mt * 16 + lr;
                af[mt][0] = f2tf(As[rA * 36 + kc]);
                af[mt][1] = f2tf(As[(rA + 8) * 36 + kc]);
                af[mt][2] = f2tf(As[rA * 36 + kc + 4]);
                af[mt][3] = f2tf(As[(rA + 8) * 36 + kc + 4]);
            }
#pragma unroll
            for (int mt = 0; mt < 4; mt++)
#pragma unroll
                for (int n8 = 0; n8 < 4; n8++)
                    mma1688_tf32(acc[mt][n8], af[mt], bf[n8]);
        }
    }

    int mBase = row0 + warpM * 64 + (lane >> 2);
    int nBase = col0 + warpN * 32 + (lane & 3) * 2;
#pragma unroll
    for (int mt = 0; mt < 4; mt++)
#pragma unroll
        for (int n8 = 0; n8 < 4; n8++) {
            int m = mBase + mt * 16;
            int n = nBase + n8 * 8;
            *(float2*)(C + (size_t)m * N + n) =
                make_float2(acc[mt][n8][0], acc[mt][n8][1]);
            *(float2*)(C + (size_t)(m + 8) * N + n) =
                make_float2(acc[mt][n8][2], acc[mt][n8][3]);
        }
}

// ---------------- bf16 3-term GEMM (output projection) --------------------
// 256x128 tile, BK=64, cp.async 2-stage (round-5 proven path).
#define GS_STAGE 98304
#define GS_SMEM  (2 * GS_STAGE)

__global__ __launch_bounds__(256, 1)
void gemm_bf16(const __nv_bfloat16* __restrict__ Ah, const __nv_bfloat16* __restrict__ Al,
               const __nv_bfloat16* __restrict__ Bh, const __nv_bfloat16* __restrict__ Bl,
               const float* __restrict__ bias, float* __restrict__ C,
               int M, int N, int K)
{
    extern __shared__ __align__(1024) char smem[];
    const uint32_t smu = smem_to_u32(smem);
    const int tid = threadIdx.x;
    const int wid = tid >> 5, lane = tid & 31;
    const int warpM = wid & 3, warpN = wid >> 2;
    const int row0 = blockIdx.y * 256;
    const int col0 = blockIdx.x * 128;
    const int KS = K >> 6;

    float acc[4][8][4];
#pragma unroll
    for (int i = 0; i < 4; i++)
#pragma unroll
        for (int j = 0; j < 8; j++)
#pragma unroll
            for (int t = 0; t < 4; t++) acc[i][j][t] = 0.f;

    auto prefetch = [&](int ks, int buf) {
        uint32_t sb = smu + (uint32_t)buf * GS_STAGE;
        int q = tid & 7;
        int rbase = tid >> 3;
        const __nv_bfloat16* pA[2] = { Ah + (size_t)row0 * K + ks * 64,
                                       Al + (size_t)row0 * K + ks * 64 };
        const __nv_bfloat16* pB[2] = { Bh + (size_t)col0 * K + ks * 64,
                                       Bl + (size_t)col0 * K + ks * 64 };
#pragma unroll
        for (int pl = 0; pl < 2; pl++) {
#pragma unroll
            for (int i = 0; i < 8; i++) {
                int r = (i << 5) + rbase;
                const void* gp = pA[pl] + (size_t)r * K + q * 8;
                uint32_t sa = sb + pl * 32768 + sw128((uint32_t)(r * 128 + q * 16));
                asm volatile("cp.async.cg.shared.global [%0], [%1], 16;" :: "r"(sa), "l"(gp));
            }
        }
#pragma unroll
        for (int pl = 0; pl < 2; pl++) {
#pragma unroll
            for (int i = 0; i < 4; i++) {
                int r = (i << 5) + rbase;
                const void* gp = pB[pl] + (size_t)r * K + q * 8;
                uint32_t sa = sb + 65536 + pl * 16384 + sw128((uint32_t)(r * 128 + q * 16));
                asm volatile("cp.async.cg.shared.global [%0], [%1], 16;" :: "r"(sa), "l"(gp));
            }
        }
    };

    auto compute_k16 = [&](uint32_t sbase, int kk) {
        uint32_t ah[4][4], al[4][4], bh[4][4], bl[4][4];
        int aRow = warpM * 64 + (lane & 15);
        int aK2 = (kk * 16 + ((lane & 16) ? 8 : 0)) * 2;
#pragma unroll
        for (int mt = 0; mt < 4; mt++) {
            uint32_t off = sw128((uint32_t)((aRow + mt * 16) * 128 + aK2));
            LDSM_X4(ah[mt][0], ah[mt][1], ah[mt][2], ah[mt][3], sbase + off);
            LDSM_X4(al[mt][0], al[mt][1], al[mt][2], al[mt][3], sbase + 32768 + off);
        }
        int bRow = warpN * 64 + (lane & 7) + ((lane & 16) ? 8 : 0);
        int bK2 = (kk * 16 + ((lane & 8) ? 8 : 0)) * 2;
#pragma unroll
        for (int pr = 0; pr < 4; pr++) {
            uint32_t off = sw128((uint32_t)((bRow + pr * 16) * 128 + bK2));
            LDSM_X4(bh[pr][0], bh[pr][1], bh[pr][2], bh[pr][3], sbase + 65536 + off);
            LDSM_X4(bl[pr][0], bl[pr][1], bl[pr][2], bl[pr][3], sbase + 81920 + off);
        }
#pragma unroll
        for (int mt = 0; mt < 4; mt++)
#pragma unroll
            for (int nt = 0; nt < 8; nt++) {
                const uint32_t* bhp = &bh[nt >> 1][(nt & 1) * 2];
                const uint32_t* blp = &bl[nt >> 1][(nt & 1) * 2];
                mma16816(acc[mt][nt], ah[mt], bhp);
                mma16816(acc[mt][nt], ah[mt], blp);
                mma16816(acc[mt][nt], al[mt], bhp);
            }
    };

    prefetch(0, 0);
    asm volatile("cp.async.commit_group;" ::: "memory");
    prefetch(1, 1);
    asm volatile("cp.async.commit_group;" ::: "memory");

    for (int ks = 0; ks < KS; ks++) {
        asm volatile("cp.async.wait_group 1;" ::: "memory");
        __syncthreads();
        uint32_t sbase = smu + (uint32_t)(ks & 1) * GS_STAGE;
#pragma unroll
        for (int kk = 0; kk < 4; kk++) compute_k16(sbase, kk);
        __syncthreads();
        if (ks + 2 < KS) prefetch(ks + 2, ks & 1);
        asm volatile("cp.async.commit_group;" ::: "memory");
    }

    int mBase = row0 + warpM * 64 + (lane >> 2);
    int nBase = col0 + warpN * 64 + (lane & 3) * 2;
#pragma unroll
    for (int mt = 0; mt < 4; mt++)
#pragma unroll
        for (int nt = 0; nt < 8; nt++) {
            int m = mBase + mt * 16;
            int n = nBase + nt * 8;
            float2 v0 = make_float2(acc[mt][nt][0], acc[mt][nt][1]);
            float2 v1 = make_float2(acc[mt][nt][2], acc[mt][nt][3]);
            float b0 = bias[n], b1 = bias[n + 1];
            v0.x += b0; v0.y += b1; v1.x += b0; v1.y += b1;
            *(float2*)(C + (size_t)m * N + n) = v0;
            *(float2*)(C + (size_t)(m + 8) * N + n) = v1;
        }
}

// ---------------- Fused pooling (levels 1..7) ----------------
__global__ __launch_bounds__(256)
void pool_fused(const float* __restrict__ qkv)
{
    __shared__ float sA[64][192];
    __shared__ float sB[32][192];

    int c  = blockIdx.x;
    int bh = blockIdx.y;
    int b = bh >> 3, h = bh & 7;
    int tid = threadIdx.x;
    int d = tid & 63, seg = tid >> 6;
    size_t poolbase = (size_t)bh * (POOLROWS * 64);

    for (int i = 0; i < 16; i++) {
        int li = seg * 16 + i;
        int grow = c * 128 + 2 * li;
        size_t base = ((size_t)(b * 4096 + grow)) * QKVW + h * 64 + d;
        float q = 0.0625f * (qkv[base] + qkv[base + QKVW]);
        float k = 0.5f * (qkv[base + 512] + qkv[base + 512 + QKVW]);
        float v = qkv[base + 1024] + qkv[base + 1024 + QKVW];
        sA[li][d] = q; sA[li][64 + d] = k; sA[li][128 + d] = v;
        size_t dst = poolbase + (size_t)(c * 64 + li) * 64 + d;
        g_poolq[dst] = q; g_poolk[dst] = k; g_poolv[dst] = v;
    }
    __syncthreads();

    for (int l = 2; l <= 7; l++) {
        int nl = 64 >> (l - 1);
        int offL = 4096 - (8192 >> l);
        bool srcA = (l & 1) == 0;
        for (int idx = tid; idx < nl * 64; idx += 256) {
            int i = idx >> 6, dd = idx & 63;
            float q0, q1, k0, k1, v0, v1;
            if (srcA) {
                q0 = sA[2 * i][dd];       q1 = sA[2 * i + 1][dd];
                k0 = sA[2 * i][64 + dd];  k1 = sA[2 * i + 1][64 + dd];
                v0 = sA[2 * i][128 + dd]; v1 = sA[2 * i + 1][128 + dd];
            } else {
                q0 = sB[2 * i][dd];       q1 = sB[2 * i + 1][dd];
                k0 = sB[2 * i][64 + dd];  k1 = sB[2 * i + 1][64 + dd];
                v0 = sB[2 * i][128 + dd]; v1 = sB[2 * i + 1][128 + dd];
            }
            float q = 0.5f * (q0 + q1);
            float k = 0.5f * (k0 + k1);
            float v = v0 + v1;
            if (srcA) { sB[i][dd] = q; sB[i][64 + dd] = k; sB[i][128 + dd] = v; }
            else      { sA[i][dd] = q; sA[i][64 + dd] = k; sA[i][128 + dd] = v; }
            size_t dst = poolbase + (size_t)(offL + c * nl + i) * 64 + dd;
            g_poolq[dst] = q; g_poolk[dst] = k; g_poolv[dst] = v;
        }
        __syncthreads();
    }
}

// ---------------- Block attention (vectorized float4) ----------------
__global__ __launch_bounds__(256)
void attn_blocks(const float* __restrict__ qkv)
{
    __shared__ float4 sk[8][16][16];
    __shared__ float4 sv[8][16][16];
    int warp = threadIdx.x >> 5;
    int lane = threadIdx.x & 31;
    int wg = blockIdx.x * 8 + warp;

    int bh = wg / 510;
    int r  = wg - bh * 510;
    int level = 0, nb = 256;
    while (r >= nb) { r -= nb; nb >>= 1; level++; }
    int blk = r;
    int b = bh >> 3, h = bh & 7;
    int kblk = (level == 0) ? blk : (blk ^ 1);

    if (level == 0) {
        const float* kbase = qkv + ((size_t)(b * 4096 + kblk * 16)) * QKVW + 512 + h * 64;
        const float* vbase = qkv + ((size_t)(b * 4096 + blk  * 16)) * QKVW + 1024 + h * 64;
#pragma unroll
        for (int i = 0; i < 8; i++) {
            int idx = lane + i * 32;
            int j = idx >> 4, qd = idx & 15;
            sk[warp][j][qd] = *((const float4*)(kbase + (size_t)j * QKVW) + qd);
            sv[warp][j][qd] = *((const float4*)(vbase + (size_t)j * QKVW) + qd);
        }
    } else {
        int off = 4096 - (8192 >> level);
        const float4* kp = (const float4*)(g_poolk + (size_t)bh * (POOLROWS * 64)
                                           + (size_t)(off + kblk * 16) * 64);
        const float4* vp = (const float4*)(g_poolv + (size_t)bh * (POOLROWS * 64)
                                           + (size_t)(off + blk * 16) * 64);
#pragma unroll
        for (int i = 0; i < 8; i++) {
            int idx = lane + i * 32;
            sk[warp][0][idx] = kp[idx];
            sv[warp][0][idx] = vp[idx];
        }
    }

    int qi = lane >> 1, hh = lane & 1;
    float4 qr[8];
    if (level == 0) {
        const float4* qp = (const float4*)(qkv + ((size_t)(b * 4096 + blk * 16 + qi)) * QKVW
                                           + h * 64 + hh * 32);
#pragma unroll
        for (int t = 0; t < 8; t++) {
            float4 v = qp[t];
            qr[t] = make_float4(0.125f * v.x, 0.125f * v.y, 0.125f * v.z, 0.125f * v.w);
        }
    } else {
        int off = 4096 - (8192 >> level);
        const float4* qp = (const float4*)(g_poolq + (size_t)bh * (POOLROWS * 64)
                                           + (size_t)(off + blk * 16 + qi) * 64 + hh * 32);
#pragma unroll
        for (int t = 0; t < 8; t++) qr[t] = qp[t];
    }
    __syncwarp();

    float Aij[16];
#pragma unroll
    for (int j = 0; j < 16; j++) {
        const float4* kr = &sk[warp][j][hh * 8];
        float p = 0.f;
#pragma unroll
        for (int t = 0; t < 8; t++) {
            float4 kv = kr[t];
            p += qr[t].x * kv.x + qr[t].y * kv.y + qr[t].z * kv.z + qr[t].w * kv.w;
        }
        p += __shfl_xor_sync(0xffffffffu, p, 1);
        Aij[j] = expf(p);
    }
    float asum = 0.f;
#pragma unroll
    for (int j = 0; j < 16; j++) asum += Aij[j];

    float4 ya[8];
#pragma unroll
    for (int t = 0; t < 8; t++) ya[t] = make_float4(0.f, 0.f, 0.f, 0.f);
#pragma unroll
    for (int j = 0; j < 16; j++) {
        float a = Aij[j];
        const float4* vr = &sv[warp][j][hh * 8];
#pragma unroll
        for (int t = 0; t < 8; t++) {
            float4 vv = vr[t];
            ya[t].x += a * vv.x; ya[t].y += a * vv.y;
            ya[t].z += a * vv.z; ya[t].w += a * vv.w;
        }
    }

    int yoff = 8192 - (8192 >> level);
    float4* yp = (float4*)(g_Y + (size_t)bh * (YROWS * 64)
                           + (size_t)(yoff + blk * 16 + qi) * 64 + hh * 32);
#pragma unroll
    for (int t = 0; t < 8; t++) yp[t] = ya[t];
    if (hh == 0)
        g_Asum[(size_t)bh * YROWS + yoff + blk * 16 + qi] = asum;
}

// ---------------- Combine (emits bf16 hi/lo att planes) ----------------
__global__ __launch_bounds__(256)
void combine_kernel()
{
    int tid = blockIdx.x * 256 + threadIdx.x;
    int qd = tid & 127;
    int m  = tid >> 7;
    int h  = qd >> 4, dq = qd & 15;
    int b = m >> 12, n = m & 4095;
    int bh = b * 8 + h;

    const float4* Yb = (const float4*)(g_Y + (size_t)bh * (YROWS * 64));
    const float* Ab = g_Asum + (size_t)bh * YROWS;

    float4 ysum = make_float4(0.f, 0.f, 0.f, 0.f);
    float asum = 0.f;
#pragma unroll
    for (int l = 0; l < 8; l++) {
        int yoff = 8192 - (8192 >> l);
        int p = yoff + (n >> l);
        float4 y = Yb[(size_t)p * 16 + dq];
        ysum.x += y.x; ysum.y += y.y; ysum.z += y.z; ysum.w += y.w;
        asum += Ab[p];
    }
    float inv = 1.f / (asum + 1e-8f);
    float4 val = make_float4(ysum.x * inv, ysum.y * inv, ysum.z * inv, ysum.w * inv);
    uint2 hi, lo; split4(val, hi, lo);
    ((uint2*)g_atth)[tid] = hi;
    ((uint2*)g_attl)[tid] = lo;
}

// ---------------- Launch ----------------
extern "C" void kernel_launch(void* const* d_in, const int* in_sizes, int n_in,
                              void* d_out, int out_size)
{
    const float* x     = (const float*)d_in[0];
    const float* w_qkv = (const float*)d_in[1];
    const float* w_out = (const float*)d_in[2];
    const float* b_out = (const float*)d_in[3];
    float* out = (float*)d_out;

    float* qkv_ptr;
    cudaGetSymbolAddress((void**)&qkv_ptr, g_qkv);
    __nv_bfloat16 *woh, *wol, *ath, *atl;
    cudaGetSymbolAddress((void**)&woh, g_woh);
    cudaGetSymbolAddress((void**)&wol, g_wol);
    cudaGetSymbolAddress((void**)&ath, g_atth);
    cudaGetSymbolAddress((void**)&atl, g_attl);

    cudaFuncSetAttribute(gemm_tf32, cudaFuncAttributeMaxDynamicSharedMemorySize, T1_SMEM);
    cudaFuncSetAttribute(gemm_bf16, cudaFuncAttributeMaxDynamicSharedMemorySize, GS_SMEM);

    // 1) Convert w_out to bf16 hi/lo
    convert_wout<<<512, 256>>>(w_out);

    // 2) QKV projection (single-pass TF32): [16384,1024] x [1536,1024]^T
    gemm_tf32<<<dim3(QKVW / 128, NROWS / 128), 256, T1_SMEM>>>(
        x, w_qkv, qkv_ptr, NROWS, QKVW, 1024);

    // 3) Fused pooling
    pool_fused<<<dim3(32, 32), 256>>>(qkv_ptr);

    // 4) Block attention
    attn_blocks<<<2040, 256>>>(qkv_ptr);

    // 5) Combine + normalize (-> bf16 hi/lo)
    combine_kernel<<<(NROWS * 128) / 256, 256>>>();

    // 6) Output projection (3-term bf16): [16384,512] x [1024,512]^T + bias
    gemm_bf16<<<dim3(1024 / 128, NROWS / 256), 256, GS_SMEM>>>(
        ath, atl, woh, wol, b_out, out, NROWS, 1024, 512);
}

// round 7
// speedup vs baseline: 1.0062x; 1.0062x over previous
#include <cuda_runtime.h>
#include <cuda_bf16.h>
#include <cstdint>

// ---------------- Problem constants ----------------
#define NROWS   16384
#define QKVW    1536
#define POOLROWS 4064
#define YROWS    8160

// ---------------- Device scratch ----------------
__device__ __align__(16) float g_qkv[(size_t)NROWS * QKVW];
__device__ __align__(16) float g_poolq[(size_t)32 * POOLROWS * 64];
__device__ __align__(16) float g_poolk[(size_t)32 * POOLROWS * 64];
__device__ __align__(16) float g_poolv[(size_t)32 * POOLROWS * 64];
__device__ __align__(16) float g_Y[(size_t)32 * YROWS * 64];
__device__ __align__(16) float g_Asum[(size_t)32 * YROWS];

// bf16 hi/lo planes
__device__ __align__(16) __nv_bfloat16 g_xh[(size_t)NROWS * 1024];
__device__ __align__(16) __nv_bfloat16 g_xl[(size_t)NROWS * 1024];
__device__ __align__(16) __nv_bfloat16 g_wqh[(size_t)QKVW * 1024];
__device__ __align__(16) __nv_bfloat16 g_wql[(size_t)QKVW * 1024];
__device__ __align__(16) __nv_bfloat16 g_woh[(size_t)1024 * 512];
__device__ __align__(16) __nv_bfloat16 g_wol[(size_t)1024 * 512];
__device__ __align__(16) __nv_bfloat16 g_atth[(size_t)NROWS * 512];
__device__ __align__(16) __nv_bfloat16 g_attl[(size_t)NROWS * 512];

// ---------------- helpers ----------------
__device__ __forceinline__ uint32_t smem_to_u32(const void* p) {
    uint32_t a;
    asm("{ .reg .u64 t; cvta.to.shared.u64 t, %1; cvt.u32.u64 %0, t; }" : "=r"(a) : "l"(p));
    return a;
}
__device__ __forceinline__ uint32_t sw128(uint32_t off) {
    return off ^ ((off >> 3) & 0x70);
}

#define LDSM_X4(r0, r1, r2, r3, addr) \
    asm volatile("ldmatrix.sync.aligned.m8n8.x4.shared.b16 {%0,%1,%2,%3}, [%4];" \
        : "=r"(r0), "=r"(r1), "=r"(r2), "=r"(r3) : "r"(addr))

__device__ __forceinline__ void mma16816(float* c, const uint32_t* a, const uint32_t* b) {
    asm volatile(
        "mma.sync.aligned.m16n8k16.row.col.f32.bf16.bf16.f32 "
        "{%0,%1,%2,%3}, {%4,%5,%6,%7}, {%8,%9}, {%0,%1,%2,%3};"
        : "+f"(c[0]), "+f"(c[1]), "+f"(c[2]), "+f"(c[3])
        : "r"(a[0]), "r"(a[1]), "r"(a[2]), "r"(a[3]), "r"(b[0]), "r"(b[1]));
}

__device__ __forceinline__ void split4(float4 v, uint2& hi, uint2& lo) {
    float f[4] = {v.x, v.y, v.z, v.w};
    uint32_t h[4], l[4];
#pragma unroll
    for (int i = 0; i < 4; i++) {
        __nv_bfloat16 hb = __float2bfloat16_rn(f[i]);
        float res = f[i] - __bfloat162float(hb);
        __nv_bfloat16 lb = __float2bfloat16_rn(res);
        h[i] = (uint32_t)__bfloat16_as_ushort(hb);
        l[i] = (uint32_t)__bfloat16_as_ushort(lb);
    }
    hi.x = h[0] | (h[1] << 16); hi.y = h[2] | (h[3] << 16);
    lo.x = l[0] | (l[1] << 16); lo.y = l[2] | (l[3] << 16);
}

// ---------------- one-shot fp32 -> bf16 hi/lo conversion ----------------
__global__ __launch_bounds__(256)
void convert_all(const float* __restrict__ x, const float* __restrict__ wq,
                 const float* __restrict__ wo)
{
    int q = blockIdx.x * 256 + threadIdx.x;
    const float* src;
    uint2 *dh, *dl;
    int local;
    if (q < 4194304) {
        src = x; dh = (uint2*)g_xh; dl = (uint2*)g_xl; local = q;
    } else if (q < 4194304 + 393216) {
        src = wq; dh = (uint2*)g_wqh; dl = (uint2*)g_wql; local = q - 4194304;
    } else {
        src = wo; dh = (uint2*)g_woh; dl = (uint2*)g_wol; local = q - 4194304 - 393216;
    }
    float4 v = *(const float4*)(src + (size_t)local * 4);
    uint2 hi, lo; split4(v, hi, lo);
    dh[local] = hi; dl[local] = lo;
}

// ---------------- mma.sync GEMM: 256x128 tile, 16 warps, BK=64 ------------
// 512 threads: 4m x 4n warps, warp tile 64x32. 2-stage cp.async.
// Stage (96KB): Ah @0 (32K), Al @32768 (32K), Bh @65536 (16K), Bl @81920 (16K)
#define GS_STAGE 98304
#define GS_SMEM  (2 * GS_STAGE)

template <int BIAS>
__global__ __launch_bounds__(512, 1)
void gemm_bf16(const __nv_bfloat16* __restrict__ Ah, const __nv_bfloat16* __restrict__ Al,
               const __nv_bfloat16* __restrict__ Bh, const __nv_bfloat16* __restrict__ Bl,
               const float* __restrict__ bias, float* __restrict__ C,
               int M, int N, int K)
{
    extern __shared__ __align__(1024) char smem[];
    const uint32_t smu = smem_to_u32(smem);
    const int tid = threadIdx.x;
    const int wid = tid >> 5, lane = tid & 31;
    const int warpM = wid & 3, warpN = wid >> 2;     // 4m x 4n, warp 64x32
    const int row0 = blockIdx.y * 256;
    const int col0 = blockIdx.x * 128;
    const int KS = K >> 6;

    float acc[4][4][4];
#pragma unroll
    for (int i = 0; i < 4; i++)
#pragma unroll
        for (int j = 0; j < 4; j++)
#pragma unroll
            for (int t = 0; t < 4; t++) acc[i][j][t] = 0.f;

    auto prefetch = [&](int ks, int buf) {
        uint32_t sb = smu + (uint32_t)buf * GS_STAGE;
        int q = tid & 7;            // 16B chunk within 128B row
        int rbase = tid >> 3;       // 64 distinct rows per pass
        const __nv_bfloat16* pA[2] = { Ah + (size_t)row0 * K + ks * 64,
                                       Al + (size_t)row0 * K + ks * 64 };
        const __nv_bfloat16* pB[2] = { Bh + (size_t)col0 * K + ks * 64,
                                       Bl + (size_t)col0 * K + ks * 64 };
#pragma unroll
        for (int pl = 0; pl < 2; pl++) {
#pragma unroll
            for (int i = 0; i < 4; i++) {           // 256 A rows
                int r = (i << 6) + rbase;
                const void* gp = pA[pl] + (size_t)r * K + q * 8;
                uint32_t sa = sb + pl * 32768 + sw128((uint32_t)(r * 128 + q * 16));
                asm volatile("cp.async.cg.shared.global [%0], [%1], 16;" :: "r"(sa), "l"(gp));
            }
        }
#pragma unroll
        for (int pl = 0; pl < 2; pl++) {
#pragma unroll
            for (int i = 0; i < 2; i++) {           // 128 B rows
                int r = (i << 6) + rbase;
                const void* gp = pB[pl] + (size_t)r * K + q * 8;
                uint32_t sa = sb + 65536 + pl * 16384 + sw128((uint32_t)(r * 128 + q * 16));
                asm volatile("cp.async.cg.shared.global [%0], [%1], 16;" :: "r"(sa), "l"(gp));
            }
        }
    };

    auto compute_k16 = [&](uint32_t sbase, int kk) {
        uint32_t ah[4][4], al[4][4], bh[2][4], bl[2][4];
        int aRow = warpM * 64 + (lane & 15);
        int aK2 = (kk * 16 + ((lane & 16) ? 8 : 0)) * 2;
#pragma unroll
        for (int mt = 0; mt < 4; mt++) {
            uint32_t off = sw128((uint32_t)((aRow + mt * 16) * 128 + aK2));
            LDSM_X4(ah[mt][0], ah[mt][1], ah[mt][2], ah[mt][3], sbase + off);
            LDSM_X4(al[mt][0], al[mt][1], al[mt][2], al[mt][3], sbase + 32768 + off);
        }
        int bRow = warpN * 32 + (lane & 7) + ((lane & 16) ? 8 : 0);
        int bK2 = (kk * 16 + ((lane & 8) ? 8 : 0)) * 2;
#pragma unroll
        for (int pr = 0; pr < 2; pr++) {
            uint32_t off = sw128((uint32_t)((bRow + pr * 16) * 128 + bK2));
            LDSM_X4(bh[pr][0], bh[pr][1], bh[pr][2], bh[pr][3], sbase + 65536 + off);
            LDSM_X4(bl[pr][0], bl[pr][1], bl[pr][2], bl[pr][3], sbase + 81920 + off);
        }
#pragma unroll
        for (int mt = 0; mt < 4; mt++)
#pragma unroll
            for (int nt = 0; nt < 4; nt++) {
                const uint32_t* bhp = &bh[nt >> 1][(nt & 1) * 2];
                const uint32_t* blp = &bl[nt >> 1][(nt & 1) * 2];
                mma16816(acc[mt][nt], ah[mt], bhp);
                mma16816(acc[mt][nt], ah[mt], blp);
                mma16816(acc[mt][nt], al[mt], bhp);
            }
    };

    prefetch(0, 0);
    asm volatile("cp.async.commit_group;" ::: "memory");
    prefetch(1, 1);
    asm volatile("cp.async.commit_group;" ::: "memory");

    for (int ks = 0; ks < KS; ks++) {
        asm volatile("cp.async.wait_group 1;" ::: "memory");
        __syncthreads();
        uint32_t sbase = smu + (uint32_t)(ks & 1) * GS_STAGE;
#pragma unroll
        for (int kk = 0; kk < 4; kk++) compute_k16(sbase, kk);
        __syncthreads();
        if (ks + 2 < KS) prefetch(ks + 2, ks & 1);
        asm volatile("cp.async.commit_group;" ::: "memory");
    }

    int mBase = row0 + warpM * 64 + (lane >> 2);
    int nBase = col0 + warpN * 32 + (lane & 3) * 2;
#pragma unroll
    for (int mt = 0; mt < 4; mt++)
#pragma unroll
        for (int nt = 0; nt < 4; nt++) {
            int m = mBase + mt * 16;
            int n = nBase + nt * 8;
            float2 v0 = make_float2(acc[mt][nt][0], acc[mt][nt][1]);
            float2 v1 = make_float2(acc[mt][nt][2], acc[mt][nt][3]);
            if (BIAS) {
                float b0 = bias[n], b1 = bias[n + 1];
                v0.x += b0; v0.y += b1; v1.x += b0; v1.y += b1;
            }
            *(float2*)(C + (size_t)m * N + n) = v0;
            *(float2*)(C + (size_t)(m + 8) * N + n) = v1;
        }
}

// ---------------- Fused pooling (levels 1..7) ----------------
__global__ __launch_bounds__(256)
void pool_fused(const float* __restrict__ qkv)
{
    __shared__ float sA[64][192];
    __shared__ float sB[32][192];

    int c  = blockIdx.x;
    int bh = blockIdx.y;
    int b = bh >> 3, h = bh & 7;
    int tid = threadIdx.x;
    int d = tid & 63, seg = tid >> 6;
    size_t poolbase = (size_t)bh * (POOLROWS * 64);

    for (int i = 0; i < 16; i++) {
        int li = seg * 16 + i;
        int grow = c * 128 + 2 * li;
        size_t base = ((size_t)(b * 4096 + grow)) * QKVW + h * 64 + d;
        float q = 0.0625f * (qkv[base] + qkv[base + QKVW]);
        float k = 0.5f * (qkv[base + 512] + qkv[base + 512 + QKVW]);
        float v = qkv[base + 1024] + qkv[base + 1024 + QKVW];
        sA[li][d] = q; sA[li][64 + d] = k; sA[li][128 + d] = v;
        size_t dst = poolbase + (size_t)(c * 64 + li) * 64 + d;
        g_poolq[dst] = q; g_poolk[dst] = k; g_poolv[dst] = v;
    }
    __syncthreads();

    for (int l = 2; l <= 7; l++) {
        int nl = 64 >> (l - 1);
        int offL = 4096 - (8192 >> l);
        bool srcA = (l & 1) == 0;
        for (int idx = tid; idx < nl * 64; idx += 256) {
            int i = idx >> 6, dd = idx & 63;
            float q0, q1, k0, k1, v0, v1;
            if (srcA) {
                q0 = sA[2 * i][dd];       q1 = sA[2 * i + 1][dd];
                k0 = sA[2 * i][64 + dd];  k1 = sA[2 * i + 1][64 + dd];
                v0 = sA[2 * i][128 + dd]; v1 = sA[2 * i + 1][128 + dd];
            } else {
                q0 = sB[2 * i][dd];       q1 = sB[2 * i + 1][dd];
                k0 = sB[2 * i][64 + dd];  k1 = sB[2 * i + 1][64 + dd];
                v0 = sB[2 * i][128 + dd]; v1 = sB[2 * i + 1][128 + dd];
            }
            float q = 0.5f * (q0 + q1);
            float k = 0.5f * (k0 + k1);
            float v = v0 + v1;
            if (srcA) { sB[i][dd] = q; sB[i][64 + dd] = k; sB[i][128 + dd] = v; }
            else      { sA[i][dd] = q; sA[i][64 + dd] = k; sA[i][128 + dd] = v; }
            size_t dst = poolbase + (size_t)(offL + c * nl + i) * 64 + dd;
            g_poolq[dst] = q; g_poolk[dst] = k; g_poolv[dst] = v;
        }
        __syncthreads();
    }
}

// ---------------- Block attention (vectorized float4) ----------------
__global__ __launch_bounds__(256)
void attn_blocks(const float* __restrict__ qkv)
{
    __shared__ float4 sk[8][16][16];
    __shared__ float4 sv[8][16][16];
    int warp = threadIdx.x >> 5;
    int lane = threadIdx.x & 31;
    int wg = blockIdx.x * 8 + warp;

    int bh = wg / 510;
    int r  = wg - bh * 510;
    int level = 0, nb = 256;
    while (r >= nb) { r -= nb; nb >>= 1; level++; }
    int blk = r;
    int b = bh >> 3, h = bh & 7;
    int kblk = (level == 0) ? blk : (blk ^ 1);

    if (level == 0) {
        const float* kbase = qkv + ((size_t)(b * 4096 + kblk * 16)) * QKVW + 512 + h * 64;
        const float* vbase = qkv + ((size_t)(b * 4096 + blk  * 16)) * QKVW + 1024 + h * 64;
#pragma unroll
        for (int i = 0; i < 8; i++) {
            int idx = lane + i * 32;
            int j = idx >> 4, qd = idx & 15;
            sk[warp][j][qd] = *((const float4*)(kbase + (size_t)j * QKVW) + qd);
            sv[warp][j][qd] = *((const float4*)(vbase + (size_t)j * QKVW) + qd);
        }
    } else {
        int off = 4096 - (8192 >> level);
        const float4* kp = (const float4*)(g_poolk + (size_t)bh * (POOLROWS * 64)
                                           + (size_t)(off + kblk * 16) * 64);
        const float4* vp = (const float4*)(g_poolv + (size_t)bh * (POOLROWS * 64)
                                           + (size_t)(off + blk * 16) * 64);
#pragma unroll
        for (int i = 0; i < 8; i++) {
            int idx = lane + i * 32;
            sk[warp][0][idx] = kp[idx];
            sv[warp][0][idx] = vp[idx];
        }
    }

    int qi = lane >> 1, hh = lane & 1;
    float4 qr[8];
    if (level == 0) {
        const float4* qp = (const float4*)(qkv + ((size_t)(b * 4096 + blk * 16 + qi)) * QKVW
                                           + h * 64 + hh * 32);
#pragma unroll
        for (int t = 0; t < 8; t++) {
            float4 v = qp[t];
            qr[t] = make_float4(0.125f * v.x, 0.125f * v.y, 0.125f * v.z, 0.125f * v.w);
        }
    } else {
        int off = 4096 - (8192 >> level);
        const float4* qp = (const float4*)(g_poolq + (size_t)bh * (POOLROWS * 64)
                                           + (size_t)(off + blk * 16 + qi) * 64 + hh * 32);
#pragma unroll
        for (int t = 0; t < 8; t++) qr[t] = qp[t];
    }
    __syncwarp();

    float Aij[16];
#pragma unroll
    for (int j = 0; j < 16; j++) {
        const float4* kr = &sk[warp][j][hh * 8];
        float p = 0.f;
#pragma unroll
        for (int t = 0; t < 8; t++) {
            float4 kv = kr[t];
            p += qr[t].x * kv.x + qr[t].y * kv.y + qr[t].z * kv.z + qr[t].w * kv.w;
        }
        p += __shfl_xor_sync(0xffffffffu, p, 1);
        Aij[j] = expf(p);
    }
    float asum = 0.f;
#pragma unroll
    for (int j = 0; j < 16; j++) asum += Aij[j];

    float4 ya[8];
#pragma unroll
    for (int t = 0; t < 8; t++) ya[t] = make_float4(0.f, 0.f, 0.f, 0.f);
#pragma unroll
    for (int j = 0; j < 16; j++) {
        float a = Aij[j];
        const float4* vr = &sv[warp][j][hh * 8];
#pragma unroll
        for (int t = 0; t < 8; t++) {
            float4 vv = vr[t];
            ya[t].x += a * vv.x; ya[t].y += a * vv.y;
            ya[t].z += a * vv.z; ya[t].w += a * vv.w;
        }
    }

    int yoff = 8192 - (8192 >> level);
    float4* yp = (float4*)(g_Y + (size_t)bh * (YROWS * 64)
                           + (size_t)(yoff + blk * 16 + qi) * 64 + hh * 32);
#pragma unroll
    for (int t = 0; t < 8; t++) yp[t] = ya[t];
    if (hh == 0)
        g_Asum[(size_t)bh * YROWS + yoff + blk * 16 + qi] = asum;
}

// ---------------- Combine (emits bf16 hi/lo att planes) ----------------
__global__ __launch_bounds__(256)
void combine_kernel()
{
    int tid = blockIdx.x * 256 + threadIdx.x;
    int qd = tid & 127;
    int m  = tid >> 7;
    int h  = qd >> 4, dq = qd & 15;
    int b = m >> 12, n = m & 4095;
    int bh = b * 8 + h;

    const float4* Yb = (const float4*)(g_Y + (size_t)bh * (YROWS * 64));
    const float* Ab = g_Asum + (size_t)bh * YROWS;

    float4 ysum = make_float4(0.f, 0.f, 0.f, 0.f);
    float asum = 0.f;
#pragma unroll
    for (int l = 0; l < 8; l++) {
        int yoff = 8192 - (8192 >> l);
        int p = yoff + (n >> l);
        float4 y = Yb[(size_t)p * 16 + dq];
        ysum.x += y.x; ysum.y += y.y; ysum.z += y.z; ysum.w += y.w;
        asum += Ab[p];
    }
    float inv = 1.f / (asum + 1e-8f);
    float4 val = make_float4(ysum.x * inv, ysum.y * inv, ysum.z * inv, ysum.w * inv);
    uint2 hi, lo; split4(val, hi, lo);
    ((uint2*)g_atth)[tid] = hi;
    ((uint2*)g_attl)[tid] = lo;
}

// ---------------- Launch ----------------
extern "C" void kernel_launch(void* const* d_in, const int* in_sizes, int n_in,
                              void* d_out, int out_size)
{
    const float* x     = (const float*)d_in[0];
    const float* w_qkv = (const float*)d_in[1];
    const float* w_out = (const float*)d_in[2];
    const float* b_out = (const float*)d_in[3];
    float* out = (float*)d_out;

    float* qkv_ptr;
    cudaGetSymbolAddress((void**)&qkv_ptr, g_qkv);
    __nv_bfloat16 *xh, *xl, *wqh, *wql, *woh, *wol, *ath, *atl;
    cudaGetSymbolAddress((void**)&xh, g_xh);
    cudaGetSymbolAddress((void**)&xl, g_xl);
    cudaGetSymbolAddress((void**)&wqh, g_wqh);
    cudaGetSymbolAddress((void**)&wql, g_wql);
    cudaGetSymbolAddress((void**)&woh, g_woh);
    cudaGetSymbolAddress((void**)&wol, g_wol);
    cudaGetSymbolAddress((void**)&ath, g_atth);
    cudaGetSymbolAddress((void**)&atl, g_attl);

    cudaFuncSetAttribute(gemm_bf16<0>, cudaFuncAttributeMaxDynamicSharedMemorySize, GS_SMEM);
    cudaFuncSetAttribute(gemm_bf16<1>, cudaFuncAttributeMaxDynamicSharedMemorySize, GS_SMEM);

    // 1) Convert inputs to bf16 hi/lo planes
    convert_all<<<18432, 256>>>(x, w_qkv, w_out);

    // 2) QKV projection: [16384,1024] x [1536,1024]^T
    gemm_bf16<0><<<dim3(QKVW / 128, NROWS / 256), 512, GS_SMEM>>>(
        xh, xl, wqh, wql, nullptr, qkv_ptr, NROWS, QKVW, 1024);

    // 3) Fused pooling
    pool_fused<<<dim3(32, 32), 256>>>(qkv_ptr);

    // 4) Block attention
    attn_blocks<<<2040, 256>>>(qkv_ptr);

    // 5) Combine + normalize (-> bf16 hi/lo)
    combine_kernel<<<(NROWS * 128) / 256, 256>>>();

    // 6) Output projection: [16384,512] x [1024,512]^T + bias
    gemm_bf16<1><<<dim3(1024 / 128, NROWS / 256), 512, GS_SMEM>>>(
        ath, atl, woh, wol, b_out, out, NROWS, 1024, 512);
}

// round 8
// speedup vs baseline: 1.9284x; 1.9165x over previous
#include <cuda_runtime.h>
#include <cuda_fp16.h>
#include <cstdint>

// ---------------- Problem constants ----------------
#define NROWS   16384
#define QKVW    1536
#define POOLROWS 4064
#define YROWS    8160

// ---------------- Device scratch ----------------
__device__ __align__(16) float g_qkv[(size_t)NROWS * QKVW];
__device__ __align__(16) float g_poolq[(size_t)32 * POOLROWS * 64];
__device__ __align__(16) float g_poolk[(size_t)32 * POOLROWS * 64];
__device__ __align__(16) float g_poolv[(size_t)32 * POOLROWS * 64];
__device__ __align__(16) float g_Y[(size_t)32 * YROWS * 64];
__device__ __align__(16) float g_Asum[(size_t)32 * YROWS];

// fp16 planes
__device__ __align__(16) __half g_xh[(size_t)NROWS * 1024];
__device__ __align__(16) __half g_wqh[(size_t)QKVW * 1024];
__device__ __align__(16) __half g_woh[(size_t)1024 * 512];
__device__ __align__(16) __half g_atth[(size_t)NROWS * 512];

// ---------------- helpers ----------------
__device__ __forceinline__ uint32_t smem_to_u32(const void* p) {
    uint32_t a;
    asm("{ .reg .u64 t; cvta.to.shared.u64 t, %1; cvt.u32.u64 %0, t; }" : "=r"(a) : "l"(p));
    return a;
}
__device__ __forceinline__ uint32_t sw128(uint32_t off) {
    return off ^ ((off >> 3) & 0x70);
}

#define LDSM_X4(r0, r1, r2, r3, addr) \
    asm volatile("ldmatrix.sync.aligned.m8n8.x4.shared.b16 {%0,%1,%2,%3}, [%4];" \
        : "=r"(r0), "=r"(r1), "=r"(r2), "=r"(r3) : "r"(addr))

__device__ __forceinline__ void mma16816h(float* c, const uint32_t* a, const uint32_t* b) {
    asm volatile(
        "mma.sync.aligned.m16n8k16.row.col.f32.f16.f16.f32 "
        "{%0,%1,%2,%3}, {%4,%5,%6,%7}, {%8,%9}, {%0,%1,%2,%3};"
        : "+f"(c[0]), "+f"(c[1]), "+f"(c[2]), "+f"(c[3])
        : "r"(a[0]), "r"(a[1]), "r"(a[2]), "r"(a[3]), "r"(b[0]), "r"(b[1]));
}

__device__ __forceinline__ uint2 cvt4h(float4 v) {
    uint2 r;
    __half2 lo = __floats2half2_rn(v.x, v.y);
    __half2 hi = __floats2half2_rn(v.z, v.w);
    r.x = *(uint32_t*)&lo;
    r.y = *(uint32_t*)&hi;
    return r;
}

// ---------------- one-shot fp32 -> fp16 conversion ----------------
// quads: x 4194304 | w_qkv 393216 | w_out 131072  (total 4718592)
__global__ __launch_bounds__(256)
void convert_all(const float* __restrict__ x, const float* __restrict__ wq,
                 const float* __restrict__ wo)
{
    int q = blockIdx.x * 256 + threadIdx.x;
    const float* src;
    uint2* dst;
    int local;
    if (q < 4194304) {
        src = x; dst = (uint2*)g_xh; local = q;
    } else if (q < 4194304 + 393216) {
        src = wq; dst = (uint2*)g_wqh; local = q - 4194304;
    } else {
        src = wo; dst = (uint2*)g_woh; local = q - 4194304 - 393216;
    }
    float4 v = *(const float4*)(src + (size_t)local * 4);
    dst[local] = cvt4h(v);
}

// ---------------- fp16 GEMM: C[M,N] = A[M,K]*B[N,K]^T (+bias) -------------
// 128x128 tile, BK=64, 8 warps (2m x 4n, 64x32 warp tiles), 3-stage cp.async,
// 2 CTAs/SM. Stage (32KB): A @0 (16KB), B @16384 (16KB). SW128 rows of 64 halfs.
#define GS_STAGE 32768
#define GS_SMEM  (3 * GS_STAGE)

template <int BIAS>
__global__ __launch_bounds__(256, 2)
void gemm_fp16(const __half* __restrict__ A, const __half* __restrict__ B,
               const float* __restrict__ bias, float* __restrict__ C,
               int M, int N, int K)
{
    extern __shared__ __align__(1024) char smem[];
    const uint32_t smu = smem_to_u32(smem);
    const int tid = threadIdx.x;
    const int wid = tid >> 5, lane = tid & 31;
    const int warpM = wid & 1, warpN = wid >> 1;
    const int row0 = blockIdx.y * 128;
    const int col0 = blockIdx.x * 128;
    const int KS = K >> 6;

    float acc[4][4][4];
#pragma unroll
    for (int i = 0; i < 4; i++)
#pragma unroll
        for (int j = 0; j < 4; j++)
#pragma unroll
            for (int t = 0; t < 4; t++) acc[i][j][t] = 0.f;

    auto prefetch = [&](int ks, int buf) {
        uint32_t sb = smu + (uint32_t)buf * GS_STAGE;
        int q = tid & 7;
        int rbase = tid >> 3;                      // 32 rows per pass
        const __half* pA = A + (size_t)row0 * K + ks * 64;
        const __half* pB = B + (size_t)col0 * K + ks * 64;
#pragma unroll
        for (int i = 0; i < 4; i++) {
            int r = (i << 5) + rbase;
            const void* gp = pA + (size_t)r * K + q * 8;
            uint32_t sa = sb + sw128((uint32_t)(r * 128 + q * 16));
            asm volatile("cp.async.cg.shared.global [%0], [%1], 16;" :: "r"(sa), "l"(gp));
        }
#pragma unroll
        for (int i = 0; i < 4; i++) {
            int r = (i << 5) + rbase;
            const void* gp = pB + (size_t)r * K + q * 8;
            uint32_t sa = sb + 16384 + sw128((uint32_t)(r * 128 + q * 16));
            asm volatile("cp.async.cg.shared.global [%0], [%1], 16;" :: "r"(sa), "l"(gp));
        }
    };

    auto compute_k16 = [&](uint32_t sbase, int kk) {
        uint32_t ah[4][4], bh[2][4];
        int aRow = warpM * 64 + (lane & 15);
        int aK2 = (kk * 16 + ((lane & 16) ? 8 : 0)) * 2;
#pragma unroll
        for (int mt = 0; mt < 4; mt++) {
            uint32_t off = sw128((uint32_t)((aRow + mt * 16) * 128 + aK2));
            LDSM_X4(ah[mt][0], ah[mt][1], ah[mt][2], ah[mt][3], sbase + off);
        }
        int bRow = warpN * 32 + (lane & 7) + ((lane & 16) ? 8 : 0);
        int bK2 = (kk * 16 + ((lane & 8) ? 8 : 0)) * 2;
#pragma unroll
        for (int pr = 0; pr < 2; pr++) {
            uint32_t off = sw128((uint32_t)((bRow + pr * 16) * 128 + bK2));
            LDSM_X4(bh[pr][0], bh[pr][1], bh[pr][2], bh[pr][3], sbase + 16384 + off);
        }
#pragma unroll
        for (int mt = 0; mt < 4; mt++)
#pragma unroll
            for (int nt = 0; nt < 4; nt++)
                mma16816h(acc[mt][nt], ah[mt], &bh[nt >> 1][(nt & 1) * 2]);
    };

    prefetch(0, 0);
    asm volatile("cp.async.commit_group;" ::: "memory");
    prefetch(1, 1);
    asm volatile("cp.async.commit_group;" ::: "memory");
    prefetch(2, 2);
    asm volatile("cp.async.commit_group;" ::: "memory");

    int buf = 0;
    for (int ks = 0; ks < KS; ks++) {
        asm volatile("cp.async.wait_group 2;" ::: "memory");
        __syncthreads();
        uint32_t sbase = smu + (uint32_t)buf * GS_STAGE;
#pragma unroll
        for (int kk = 0; kk < 4; kk++) compute_k16(sbase, kk);
        __syncthreads();
        if (ks + 3 < KS) prefetch(ks + 3, buf);
        asm volatile("cp.async.commit_group;" ::: "memory");
        buf = (buf + 1 == 3) ? 0 : buf + 1;
    }

    int mBase = row0 + warpM * 64 + (lane >> 2);
    int nBase = col0 + warpN * 32 + (lane & 3) * 2;
#pragma unroll
    for (int mt = 0; mt < 4; mt++)
#pragma unroll
        for (int nt = 0; nt < 4; nt++) {
            int m = mBase + mt * 16;
            int n = nBase + nt * 8;
            float2 v0 = make_float2(acc[mt][nt][0], acc[mt][nt][1]);
            float2 v1 = make_float2(acc[mt][nt][2], acc[mt][nt][3]);
            if (BIAS) {
                float b0 = bias[n], b1 = bias[n + 1];
                v0.x += b0; v0.y += b1; v1.x += b0; v1.y += b1;
            }
            *(float2*)(C + (size_t)m * N + n) = v0;
            *(float2*)(C + (size_t)(m + 8) * N + n) = v1;
        }
}

// ---------------- Fused pooling (levels 1..7) ----------------
__global__ __launch_bounds__(256)
void pool_fused(const float* __restrict__ qkv)
{
    __shared__ float sA[64][192];
    __shared__ float sB[32][192];

    int c  = blockIdx.x;
    int bh = blockIdx.y;
    int b = bh >> 3, h = bh & 7;
    int tid = threadIdx.x;
    int d = tid & 63, seg = tid >> 6;
    size_t poolbase = (size_t)bh * (POOLROWS * 64);

    for (int i = 0; i < 16; i++) {
        int li = seg * 16 + i;
        int grow = c * 128 + 2 * li;
        size_t base = ((size_t)(b * 4096 + grow)) * QKVW + h * 64 + d;
        float q = 0.0625f * (qkv[base] + qkv[base + QKVW]);
        float k = 0.5f * (qkv[base + 512] + qkv[base + 512 + QKVW]);
        float v = qkv[base + 1024] + qkv[base + 1024 + QKVW];
        sA[li][d] = q; sA[li][64 + d] = k; sA[li][128 + d] = v;
        size_t dst = poolbase + (size_t)(c * 64 + li) * 64 + d;
        g_poolq[dst] = q; g_poolk[dst] = k; g_poolv[dst] = v;
    }
    __syncthreads();

    for (int l = 2; l <= 7; l++) {
        int nl = 64 >> (l - 1);
        int offL = 4096 - (8192 >> l);
        bool srcA = (l & 1) == 0;
        for (int idx = tid; idx < nl * 64; idx += 256) {
            int i = idx >> 6, dd = idx & 63;
            float q0, q1, k0, k1, v0, v1;
            if (srcA) {
                q0 = sA[2 * i][dd];       q1 = sA[2 * i + 1][dd];
                k0 = sA[2 * i][64 + dd];  k1 = sA[2 * i + 1][64 + dd];
                v0 = sA[2 * i][128 + dd]; v1 = sA[2 * i + 1][128 + dd];
            } else {
                q0 = sB[2 * i][dd];       q1 = sB[2 * i + 1][dd];
                k0 = sB[2 * i][64 + dd];  k1 = sB[2 * i + 1][64 + dd];
                v0 = sB[2 * i][128 + dd]; v1 = sB[2 * i + 1][128 + dd];
            }
            float q = 0.5f * (q0 + q1);
            float k = 0.5f * (k0 + k1);
            float v = v0 + v1;
            if (srcA) { sB[i][dd] = q; sB[i][64 + dd] = k; sB[i][128 + dd] = v; }
            else      { sA[i][dd] = q; sA[i][64 + dd] = k; sA[i][128 + dd] = v; }
            size_t dst = poolbase + (size_t)(offL + c * nl + i) * 64 + dd;
            g_poolq[dst] = q; g_poolk[dst] = k; g_poolv[dst] = v;
        }
        __syncthreads();
    }
}

// ---------------- Block attention (vectorized float4) ----------------
__global__ __launch_bounds__(256)
void attn_blocks(const float* __restrict__ qkv)
{
    __shared__ float4 sk[8][16][16];
    __shared__ float4 sv[8][16][16];
    int warp = threadIdx.x >> 5;
    int lane = threadIdx.x & 31;
    int wg = blockIdx.x * 8 + warp;

    int bh = wg / 510;
    int r  = wg - bh * 510;
    int level = 0, nb = 256;
    while (r >= nb) { r -= nb; nb >>= 1; level++; }
    int blk = r;
    int b = bh >> 3, h = bh & 7;
    int kblk = (level == 0) ? blk : (blk ^ 1);

    if (level == 0) {
        const float* kbase = qkv + ((size_t)(b * 4096 + kblk * 16)) * QKVW + 512 + h * 64;
        const float* vbase = qkv + ((size_t)(b * 4096 + blk  * 16)) * QKVW + 1024 + h * 64;
#pragma unroll
        for (int i = 0; i < 8; i++) {
            int idx = lane + i * 32;
            int j = idx >> 4, qd = idx & 15;
            sk[warp][j][qd] = *((const float4*)(kbase + (size_t)j * QKVW) + qd);
            sv[warp][j][qd] = *((const float4*)(vbase + (size_t)j * QKVW) + qd);
        }
    } else {
        int off = 4096 - (8192 >> level);
        const float4* kp = (const float4*)(g_poolk + (size_t)bh * (POOLROWS * 64)
                                           + (size_t)(off + kblk * 16) * 64);
        const float4* vp = (const float4*)(g_poolv + (size_t)bh * (POOLROWS * 64)
                                           + (size_t)(off + blk * 16) * 64);
#pragma unroll
        for (int i = 0; i < 8; i++) {
            int idx = lane + i * 32;
            sk[warp][0][idx] = kp[idx];
            sv[warp][0][idx] = vp[idx];
        }
    }

    int qi = lane >> 1, hh = lane & 1;
    float4 qr[8];
    if (level == 0) {
        const float4* qp = (const float4*)(qkv + ((size_t)(b * 4096 + blk * 16 + qi)) * QKVW
                                           + h * 64 + hh * 32);
#pragma unroll
        for (int t = 0; t < 8; t++) {
            float4 v = qp[t];
            qr[t] = make_float4(0.125f * v.x, 0.125f * v.y, 0.125f * v.z, 0.125f * v.w);
        }
    } else {
        int off = 4096 - (8192 >> level);
        const float4* qp = (const float4*)(g_poolq + (size_t)bh * (POOLROWS * 64)
                                           + (size_t)(off + blk * 16 + qi) * 64 + hh * 32);
#pragma unroll
        for (int t = 0; t < 8; t++) qr[t] = qp[t];
    }
    __syncwarp();

    float Aij[16];
#pragma unroll
    for (int j = 0; j < 16; j++) {
        const float4* kr = &sk[warp][j][hh * 8];
        float p = 0.f;
#pragma unroll
        for (int t = 0; t < 8; t++) {
            float4 kv = kr[t];
            p += qr[t].x * kv.x + qr[t].y * kv.y + qr[t].z * kv.z + qr[t].w * kv.w;
        }
        p += __shfl_xor_sync(0xffffffffu, p, 1);
        Aij[j] = expf(p);
    }
    float asum = 0.f;
#pragma unroll
    for (int j = 0; j < 16; j++) asum += Aij[j];

    float4 ya[8];
#pragma unroll
    for (int t = 0; t < 8; t++) ya[t] = make_float4(0.f, 0.f, 0.f, 0.f);
#pragma unroll
    for (int j = 0; j < 16; j++) {
        float a = Aij[j];
        const float4* vr = &sv[warp][j][hh * 8];
#pragma unroll
        for (int t = 0; t < 8; t++) {
            float4 vv = vr[t];
            ya[t].x += a * vv.x; ya[t].y += a * vv.y;
            ya[t].z += a * vv.z; ya[t].w += a * vv.w;
        }
    }

    int yoff = 8192 - (8192 >> level);
    float4* yp = (float4*)(g_Y + (size_t)bh * (YROWS * 64)
                           + (size_t)(yoff + blk * 16 + qi) * 64 + hh * 32);
#pragma unroll
    for (int t = 0; t < 8; t++) yp[t] = ya[t];
    if (hh == 0)
        g_Asum[(size_t)bh * YROWS + yoff + blk * 16 + qi] = asum;
}

// ---------------- Combine (emits fp16 att plane) ----------------
__global__ __launch_bounds__(256)
void combine_kernel()
{
    int tid = blockIdx.x * 256 + threadIdx.x;
    int qd = tid & 127;
    int m  = tid >> 7;
    int h  = qd >> 4, dq = qd & 15;
    int b = m >> 12, n = m & 4095;
    int bh = b * 8 + h;

    const float4* Yb = (const float4*)(g_Y + (size_t)bh * (YROWS * 64));
    const float* Ab = g_Asum + (size_t)bh * YROWS;

    float4 ysum = make_float4(0.f, 0.f, 0.f, 0.f);
    float asum = 0.f;
#pragma unroll
    for (int l = 0; l < 8; l++) {
        int yoff = 8192 - (8192 >> l);
        int p = yoff + (n >> l);
        float4 y = Yb[(size_t)p * 16 + dq];
        ysum.x += y.x; ysum.y += y.y; ysum.z += y.z; ysum.w += y.w;
        asum += Ab[p];
    }
    float inv = 1.f / (asum + 1e-8f);
    float4 val = make_float4(ysum.x * inv, ysum.y * inv, ysum.z * inv, ysum.w * inv);
    ((uint2*)g_atth)[tid] = cvt4h(val);
}

// ---------------- Launch ----------------
extern "C" void kernel_launch(void* const* d_in, const int* in_sizes, int n_in,
                              void* d_out, int out_size)
{
    const float* x     = (const float*)d_in[0];
    const float* w_qkv = (const float*)d_in[1];
    const float* w_out = (const float*)d_in[2];
    const float* b_out = (const float*)d_in[3];
    float* out = (float*)d_out;

    float* qkv_ptr;
    cudaGetSymbolAddress((void**)&qkv_ptr, g_qkv);
    __half *xh, *wqh, *woh, *ath;
    cudaGetSymbolAddress((void**)&xh, g_xh);
    cudaGetSymbolAddress((void**)&wqh, g_wqh);
    cudaGetSymbolAddress((void**)&woh, g_woh);
    cudaGetSymbolAddress((void**)&ath, g_atth);

    cudaFuncSetAttribute(gemm_fp16<0>, cudaFuncAttributeMaxDynamicSharedMemorySize, GS_SMEM);
    cudaFuncSetAttribute(gemm_fp16<1>, cudaFuncAttributeMaxDynamicSharedMemorySize, GS_SMEM);

    // 1) Convert inputs to fp16
    convert_all<<<18432, 256>>>(x, w_qkv, w_out);

    // 2) QKV projection: [16384,1024] x [1536,1024]^T
    gemm_fp16<0><<<dim3(QKVW / 128, NROWS / 128), 256, GS_SMEM>>>(
        xh, wqh, nullptr, qkv_ptr, NROWS, QKVW, 1024);

    // 3) Fused pooling
    pool_fused<<<dim3(32, 32), 256>>>(qkv_ptr);

    // 4) Block attention
    attn_blocks<<<2040, 256>>>(qkv_ptr);

    // 5) Combine + normalize (-> fp16)
    combine_kernel<<<(NROWS * 128) / 256, 256>>>();

    // 6) Output projection: [16384,512] x [1024,512]^T + bias
    gemm_fp16<1><<<dim3(1024 / 128, NROWS / 128), 256, GS_SMEM>>>(
        ath, woh, b_out, out, NROWS, 1024, 512);
}

// round 9
// speedup vs baseline: 2.5349x; 1.3145x over previous
#include <cuda_runtime.h>
#include <cuda_fp16.h>
#include <cstdint>

// ---------------- Problem constants ----------------
#define NROWS   16384
#define QKVW    1536
#define POOLROWS 4064
#define YROWS    8160

// ---------------- Device scratch ----------------
__device__ __align__(16) float g_Y[(size_t)32 * YROWS * 64];
__device__ __align__(16) float g_Asum[(size_t)32 * YROWS];

__device__ __align__(16) __half g_qkv16[(size_t)NROWS * QKVW];
__device__ __align__(16) __half g_poolq[(size_t)32 * POOLROWS * 64];
__device__ __align__(16) __half g_poolk[(size_t)32 * POOLROWS * 64];
__device__ __align__(16) __half g_poolv[(size_t)32 * POOLROWS * 64];

__device__ __align__(16) __half g_xh[(size_t)NROWS * 1024];
__device__ __align__(16) __half g_wqh[(size_t)QKVW * 1024];
__device__ __align__(16) __half g_woh[(size_t)1024 * 512];
__device__ __align__(16) __half g_atth[(size_t)NROWS * 512];

// ---------------- helpers ----------------
__device__ __forceinline__ uint32_t smem_to_u32(const void* p) {
    uint32_t a;
    asm("{ .reg .u64 t; cvta.to.shared.u64 t, %1; cvt.u32.u64 %0, t; }" : "=r"(a) : "l"(p));
    return a;
}
__device__ __forceinline__ uint32_t sw128(uint32_t off) {
    return off ^ ((off >> 3) & 0x70);
}

#define LDSM_X4(r0, r1, r2, r3, addr) \
    asm volatile("ldmatrix.sync.aligned.m8n8.x4.shared.b16 {%0,%1,%2,%3}, [%4];" \
        : "=r"(r0), "=r"(r1), "=r"(r2), "=r"(r3) : "r"(addr))
#define LDSM_X4_T(r0, r1, r2, r3, addr) \
    asm volatile("ldmatrix.sync.aligned.m8n8.x4.trans.shared.b16 {%0,%1,%2,%3}, [%4];" \
        : "=r"(r0), "=r"(r1), "=r"(r2), "=r"(r3) : "r"(addr))

__device__ __forceinline__ void mma16816h(float* c, const uint32_t* a, const uint32_t* b) {
    asm volatile(
        "mma.sync.aligned.m16n8k16.row.col.f32.f16.f16.f32 "
        "{%0,%1,%2,%3}, {%4,%5,%6,%7}, {%8,%9}, {%0,%1,%2,%3};"
        : "+f"(c[0]), "+f"(c[1]), "+f"(c[2]), "+f"(c[3])
        : "r"(a[0]), "r"(a[1]), "r"(a[2]), "r"(a[3]), "r"(b[0]), "r"(b[1]));
}

__device__ __forceinline__ uint2 cvt4h(float4 v) {
    uint2 r;
    __half2 lo = __floats2half2_rn(v.x, v.y);
    __half2 hi = __floats2half2_rn(v.z, v.w);
    r.x = *(uint32_t*)&lo;
    r.y = *(uint32_t*)&hi;
    return r;
}

// ---------------- one-shot fp32 -> fp16 conversion ----------------
__global__ __launch_bounds__(256)
void convert_all(const float* __restrict__ x, const float* __restrict__ wq,
                 const float* __restrict__ wo)
{
    int q = blockIdx.x * 256 + threadIdx.x;
    const float* src;
    uint2* dst;
    int local;
    if (q < 4194304) {
        src = x; dst = (uint2*)g_xh; local = q;
    } else if (q < 4194304 + 393216) {
        src = wq; dst = (uint2*)g_wqh; local = q - 4194304;
    } else {
        src = wo; dst = (uint2*)g_woh; local = q - 4194304 - 393216;
    }
    float4 v = *(const float4*)(src + (size_t)local * 4);
    dst[local] = cvt4h(v);
}

// ---------------- fp16 GEMM ------------------------------------------------
// C[M,N] = A[M,K]*B[N,K]^T. 128x128 tile, BK=64, 8 warps, 3-stage, 2 CTAs/SM.
// OUT16: emit fp16 C with 0.125 scale on cols < 512 (qkv path).
// else : emit fp32 C + bias (final output path).
#define GS_STAGE 32768
#define GS_SMEM  (3 * GS_STAGE)

template <int OUT16>
__global__ __launch_bounds__(256, 2)
void gemm_fp16(const __half* __restrict__ A, const __half* __restrict__ B,
               const float* __restrict__ bias, float* __restrict__ C,
               __half* __restrict__ C16, int M, int N, int K)
{
    extern __shared__ __align__(1024) char smem[];
    const uint32_t smu = smem_to_u32(smem);
    const int tid = threadIdx.x;
    const int wid = tid >> 5, lane = tid & 31;
    const int warpM = wid & 1, warpN = wid >> 1;
    const int row0 = blockIdx.y * 128;
    const int col0 = blockIdx.x * 128;
    const int KS = K >> 6;

    float acc[4][4][4];
#pragma unroll
    for (int i = 0; i < 4; i++)
#pragma unroll
        for (int j = 0; j < 4; j++)
#pragma unroll
            for (int t = 0; t < 4; t++) acc[i][j][t] = 0.f;

    auto prefetch = [&](int ks, int buf) {
        uint32_t sb = smu + (uint32_t)buf * GS_STAGE;
        int q = tid & 7;
        int rbase = tid >> 3;
        const __half* pA = A + (size_t)row0 * K + ks * 64;
        const __half* pB = B + (size_t)col0 * K + ks * 64;
#pragma unroll
        for (int i = 0; i < 4; i++) {
            int r = (i << 5) + rbase;
            const void* gp = pA + (size_t)r * K + q * 8;
            uint32_t sa = sb + sw128((uint32_t)(r * 128 + q * 16));
            asm volatile("cp.async.cg.shared.global [%0], [%1], 16;" :: "r"(sa), "l"(gp));
        }
#pragma unroll
        for (int i = 0; i < 4; i++) {
            int r = (i << 5) + rbase;
            const void* gp = pB + (size_t)r * K + q * 8;
            uint32_t sa = sb + 16384 + sw128((uint32_t)(r * 128 + q * 16));
            asm volatile("cp.async.cg.shared.global [%0], [%1], 16;" :: "r"(sa), "l"(gp));
        }
    };

    auto compute_k16 = [&](uint32_t sbase, int kk) {
        uint32_t ah[4][4], bh[2][4];
        int aRow = warpM * 64 + (lane & 15);
        int aK2 = (kk * 16 + ((lane & 16) ? 8 : 0)) * 2;
#pragma unroll
        for (int mt = 0; mt < 4; mt++) {
            uint32_t off = sw128((uint32_t)((aRow + mt * 16) * 128 + aK2));
            LDSM_X4(ah[mt][0], ah[mt][1], ah[mt][2], ah[mt][3], sbase + off);
        }
        int bRow = warpN * 32 + (lane & 7) + ((lane & 16) ? 8 : 0);
        int bK2 = (kk * 16 + ((lane & 8) ? 8 : 0)) * 2;
#pragma unroll
        for (int pr = 0; pr < 2; pr++) {
            uint32_t off = sw128((uint32_t)((bRow + pr * 16) * 128 + bK2));
            LDSM_X4(bh[pr][0], bh[pr][1], bh[pr][2], bh[pr][3], sbase + 16384 + off);
        }
#pragma unroll
        for (int mt = 0; mt < 4; mt++)
#pragma unroll
            for (int nt = 0; nt < 4; nt++)
                mma16816h(acc[mt][nt], ah[mt], &bh[nt >> 1][(nt & 1) * 2]);
    };

    prefetch(0, 0);
    asm volatile("cp.async.commit_group;" ::: "memory");
    prefetch(1, 1);
    asm volatile("cp.async.commit_group;" ::: "memory");
    prefetch(2, 2);
    asm volatile("cp.async.commit_group;" ::: "memory");

    int buf = 0;
    for (int ks = 0; ks < KS; ks++) {
        asm volatile("cp.async.wait_group 2;" ::: "memory");
        __syncthreads();
        uint32_t sbase = smu + (uint32_t)buf * GS_STAGE;
#pragma unroll
        for (int kk = 0; kk < 4; kk++) compute_k16(sbase, kk);
        __syncthreads();
        if (ks + 3 < KS) prefetch(ks + 3, buf);
        asm volatile("cp.async.commit_group;" ::: "memory");
        buf = (buf + 1 == 3) ? 0 : buf + 1;
    }

    int mBase = row0 + warpM * 64 + (lane >> 2);
    int nBase = col0 + warpN * 32 + (lane & 3) * 2;
#pragma unroll
    for (int mt = 0; mt < 4; mt++)
#pragma unroll
        for (int nt = 0; nt < 4; nt++) {
            int m = mBase + mt * 16;
            int n = nBase + nt * 8;
            if (OUT16) {
                float s = (n < 512) ? 0.125f : 1.0f;
                __half2 h0 = __floats2half2_rn(acc[mt][nt][0] * s, acc[mt][nt][1] * s);
                __half2 h1 = __floats2half2_rn(acc[mt][nt][2] * s, acc[mt][nt][3] * s);
                *(__half2*)(C16 + (size_t)m * N + n) = h0;
                *(__half2*)(C16 + (size_t)(m + 8) * N + n) = h1;
            } else {
                float2 v0 = make_float2(acc[mt][nt][0], acc[mt][nt][1]);
                float2 v1 = make_float2(acc[mt][nt][2], acc[mt][nt][3]);
                float b0 = bias[n], b1 = bias[n + 1];
                v0.x += b0; v0.y += b1; v1.x += b0; v1.y += b1;
                *(float2*)(C + (size_t)m * N + n) = v0;
                *(float2*)(C + (size_t)(m + 8) * N + n) = v1;
            }
        }
}

// ---------------- Fused pooling (levels 1..7, fp16 in/out) ----------------
__global__ __launch_bounds__(256)
void pool_fused(const __half* __restrict__ qkv)
{
    __shared__ float sA[64][192];
    __shared__ float sB[32][192];

    int c  = blockIdx.x;
    int bh = blockIdx.y;
    int b = bh >> 3, h = bh & 7;
    int tid = threadIdx.x;
    int d = tid & 63, seg = tid >> 6;
    size_t poolbase = (size_t)bh * (POOLROWS * 64);

    // Level 1 (q already carries the 0.125 scale -> mean = 0.5*(a+b))
    for (int i = 0; i < 16; i++) {
        int li = seg * 16 + i;
        int grow = c * 128 + 2 * li;
        size_t base = ((size_t)(b * 4096 + grow)) * QKVW + h * 64 + d;
        float q = 0.5f * (__half2float(qkv[base]) + __half2float(qkv[base + QKVW]));
        float k = 0.5f * (__half2float(qkv[base + 512]) + __half2float(qkv[base + 512 + QKVW]));
        float v = __half2float(qkv[base + 1024]) + __half2float(qkv[base + 1024 + QKVW]);
        sA[li][d] = q; sA[li][64 + d] = k; sA[li][128 + d] = v;
        size_t dst = poolbase + (size_t)(c * 64 + li) * 64 + d;
        g_poolq[dst] = __float2half_rn(q);
        g_poolk[dst] = __float2half_rn(k);
        g_poolv[dst] = __float2half_rn(v);
    }
    __syncthreads();

    for (int l = 2; l <= 7; l++) {
        int nl = 64 >> (l - 1);
        int offL = 4096 - (8192 >> l);
        bool srcA = (l & 1) == 0;
        for (int idx = tid; idx < nl * 64; idx += 256) {
            int i = idx >> 6, dd = idx & 63;
            float q0, q1, k0, k1, v0, v1;
            if (srcA) {
                q0 = sA[2 * i][dd];       q1 = sA[2 * i + 1][dd];
                k0 = sA[2 * i][64 + dd];  k1 = sA[2 * i + 1][64 + dd];
                v0 = sA[2 * i][128 + dd]; v1 = sA[2 * i + 1][128 + dd];
            } else {
                q0 = sB[2 * i][dd];       q1 = sB[2 * i + 1][dd];
                k0 = sB[2 * i][64 + dd];  k1 = sB[2 * i + 1][64 + dd];
                v0 = sB[2 * i][128 + dd]; v1 = sB[2 * i + 1][128 + dd];
            }
            float q = 0.5f * (q0 + q1);
            float k = 0.5f * (k0 + k1);
            float v = v0 + v1;
            if (srcA) { sB[i][dd] = q; sB[i][64 + dd] = k; sB[i][128 + dd] = v; }
            else      { sA[i][dd] = q; sA[i][64 + dd] = k; sA[i][128 + dd] = v; }
            size_t dst = poolbase + (size_t)(offL + c * nl + i) * 64 + dd;
            g_poolq[dst] = __float2half_rn(q);
            g_poolk[dst] = __float2half_rn(k);
            g_poolv[dst] = __float2half_rn(v);
        }
        __syncthreads();
    }
}

// ---------------- Block attention via mma.sync -----------------------------
// One warp per 16x16 block; 8 warps/CTA. S = q k^T (8 HMMA), exp fp32,
// A->fp16 a-frags, y = A v (8 HMMA, ldmatrix.trans on V).
__global__ __launch_bounds__(256)
void attn_mma(const __half* __restrict__ qkv)
{
    __shared__ __align__(1024) char smem[8 * 6144];   // per warp: q,k,v tiles 2KB each
    int warp = threadIdx.x >> 5;
    int lane = threadIdx.x & 31;
    int wg = blockIdx.x * 8 + warp;

    int bh = wg / 510;
    int r  = wg - bh * 510;
    int level = 0, nb = 256;
    while (r >= nb) { r -= nb; nb >>= 1; level++; }
    int blk = r;
    int b = bh >> 3, h = bh & 7;
    int kblk = (level == 0) ? blk : (blk ^ 1);

    char* st = smem + warp * 6144;
    const uint32_t su = smem_to_u32(st);

    const __half *qs, *ks, *vs;
    int stride;
    if (level == 0) {
        size_t rq = (size_t)(b * 4096 + blk * 16) * QKVW;
        size_t rk = (size_t)(b * 4096 + kblk * 16) * QKVW;
        qs = qkv + rq + h * 64;
        ks = qkv + rk + 512 + h * 64;
        vs = qkv + rq + 1024 + h * 64;
        stride = QKVW;
    } else {
        int off = 4096 - (8192 >> level);
        size_t pb = (size_t)bh * (POOLROWS * 64);
        qs = g_poolq + pb + (size_t)(off + blk * 16) * 64;
        ks = g_poolk + pb + (size_t)(off + kblk * 16) * 64;
        vs = g_poolv + pb + (size_t)(off + blk * 16) * 64;
        stride = 64;
    }

    // Stage q,k,v tiles (16 rows x 128B, SW128-swizzled)
#pragma unroll
    for (int i = 0; i < 4; i++) {
        int chunk = i * 32 + lane;
        int row = chunk >> 3, qd = chunk & 7;
        uint32_t dst = sw128((uint32_t)(row * 128 + qd * 16));
        *(float4*)(st + dst)        = *(const float4*)(qs + (size_t)row * stride + qd * 8);
        *(float4*)(st + 2048 + dst) = *(const float4*)(ks + (size_t)row * stride + qd * 8);
        *(float4*)(st + 4096 + dst) = *(const float4*)(vs + (size_t)row * stride + qd * 8);
    }
    __syncwarp();

    // S = q k^T : M=16, N=16, K=64
    float s[2][4];
#pragma unroll
    for (int j = 0; j < 2; j++)
#pragma unroll
        for (int t = 0; t < 4; t++) s[j][t] = 0.f;

    int aRow = lane & 15;
    int bRow = (lane & 7) + ((lane & 16) ? 8 : 0);
#pragma unroll
    for (int kk = 0; kk < 4; kk++) {
        uint32_t ah[4], bh[4];
        uint32_t aoff = sw128((uint32_t)(aRow * 128 + (kk * 16 + ((lane & 16) ? 8 : 0)) * 2));
        LDSM_X4(ah[0], ah[1], ah[2], ah[3], su + aoff);
        uint32_t boff = sw128((uint32_t)(bRow * 128 + (kk * 16 + ((lane & 8) ? 8 : 0)) * 2));
        LDSM_X4(bh[0], bh[1], bh[2], bh[3], su + 2048 + boff);
        mma16816h(s[0], ah, &bh[0]);
        mma16816h(s[1], ah, &bh[2]);
    }

    // exp (fp32), quantize A to fp16; use quantized values for asum too.
    float e[2][4];
    uint32_t aA[4];
#pragma unroll
    for (int j = 0; j < 2; j++) {
#pragma unroll
        for (int t = 0; t < 4; t++) {
            __half hq = __float2half_rn(expf(s[j][t]));
            e[j][t] = __half2float(hq);
        }
        __half2 p0 = __floats2half2_rn(e[j][0], e[j][1]);
        __half2 p1 = __floats2half2_rn(e[j][2], e[j][3]);
        aA[j * 2 + 0] = *(uint32_t*)&p0;   // rows r,   cols j*8 + (lane&3)*2
        aA[j * 2 + 1] = *(uint32_t*)&p1;   // rows r+8
    }
    // a-frag order for y-mma: a0=(r,c), a1=(r+8,c), a2=(r,c+8), a3=(r+8,c+8)
    uint32_t aF[4] = { aA[0], aA[1], aA[2], aA[3] };

    // asum row sums
    float sr  = e[0][0] + e[0][1] + e[1][0] + e[1][1];
    float sr8 = e[0][2] + e[0][3] + e[1][2] + e[1][3];
    sr  += __shfl_xor_sync(0xffffffffu, sr, 1);
    sr  += __shfl_xor_sync(0xffffffffu, sr, 2);
    sr8 += __shfl_xor_sync(0xffffffffu, sr8, 1);
    sr8 += __shfl_xor_sync(0xffffffffu, sr8, 2);

    // y = A v : M=16, N=64, K=16 ; V is [j][d] row-major -> ldmatrix.trans
    float y[8][4];
#pragma unroll
    for (int f = 0; f < 8; f++)
#pragma unroll
        for (int t = 0; t < 4; t++) y[f][t] = 0.f;

    int vRow = lane & 15;
    int vColBase = (lane & 16) ? 8 : 0;
#pragma unroll
    for (int vi = 0; vi < 4; vi++) {
        uint32_t vb[4];
        uint32_t voff = sw128((uint32_t)(vRow * 128 + (vColBase + vi * 16) * 2));
        LDSM_X4_T(vb[0], vb[1], vb[2], vb[3], su + 4096 + voff);
        mma16816h(y[vi * 2 + 0], aF, &vb[0]);
        mma16816h(y[vi * 2 + 1], aF, &vb[2]);
    }

    // Store Y (fp32) and Asum
    int yoff = 8192 - (8192 >> level);
    int r0 = lane >> 2;
    int c0 = (lane & 3) * 2;
    float* Ybase = g_Y + (size_t)bh * (YROWS * 64) + (size_t)(yoff + blk * 16) * 64;
#pragma unroll
    for (int f = 0; f < 8; f++) {
        int d0 = f * 8 + c0;
        *(float2*)(Ybase + (size_t)r0 * 64 + d0)       = make_float2(y[f][0], y[f][1]);
        *(float2*)(Ybase + (size_t)(r0 + 8) * 64 + d0) = make_float2(y[f][2], y[f][3]);
    }
    if ((lane & 3) == 0) {
        float* Ab = g_Asum + (size_t)bh * YROWS + yoff + blk * 16;
        Ab[r0] = sr;
        Ab[r0 + 8] = sr8;
    }
}

// ---------------- Combine (emits fp16 att plane) ----------------
__global__ __launch_bounds__(256)
void combine_kernel()
{
    int tid = blockIdx.x * 256 + threadIdx.x;
    int qd = tid & 127;
    int m  = tid >> 7;
    int h  = qd >> 4, dq = qd & 15;
    int b = m >> 12, n = m & 4095;
    int bh = b * 8 + h;

    const float4* Yb = (const float4*)(g_Y + (size_t)bh * (YROWS * 64));
    const float* Ab = g_Asum + (size_t)bh * YROWS;

    float4 ysum = make_float4(0.f, 0.f, 0.f, 0.f);
    float asum = 0.f;
#pragma unroll
    for (int l = 0; l < 8; l++) {
        int yoff = 8192 - (8192 >> l);
        int p = yoff + (n >> l);
        float4 y = Yb[(size_t)p * 16 + dq];
        ysum.x += y.x; ysum.y += y.y; ysum.z += y.z; ysum.w += y.w;
        asum += Ab[p];
    }
    float inv = 1.f / (asum + 1e-8f);
    float4 val = make_float4(ysum.x * inv, ysum.y * inv, ysum.z * inv, ysum.w * inv);
    ((uint2*)g_atth)[tid] = cvt4h(val);
}

// ---------------- Launch ----------------
extern "C" void kernel_launch(void* const* d_in, const int* in_sizes, int n_in,
                              void* d_out, int out_size)
{
    const float* x     = (const float*)d_in[0];
    const float* w_qkv = (const float*)d_in[1];
    const float* w_out = (const float*)d_in[2];
    const float* b_out = (const float*)d_in[3];
    float* out = (float*)d_out;

    __half *xh, *wqh, *woh, *ath, *qkv16;
    cudaGetSymbolAddress((void**)&xh, g_xh);
    cudaGetSymbolAddress((void**)&wqh, g_wqh);
    cudaGetSymbolAddress((void**)&woh, g_woh);
    cudaGetSymbolAddress((void**)&ath, g_atth);
    cudaGetSymbolAddress((void**)&qkv16, g_qkv16);

    cudaFuncSetAttribute(gemm_fp16<0>, cudaFuncAttributeMaxDynamicSharedMemorySize, GS_SMEM);
    cudaFuncSetAttribute(gemm_fp16<1>, cudaFuncAttributeMaxDynamicSharedMemorySize, GS_SMEM);

    // 1) Convert inputs to fp16
    convert_all<<<18432, 256>>>(x, w_qkv, w_out);

    // 2) QKV projection -> fp16 qkv (q pre-scaled 0.125)
    gemm_fp16<1><<<dim3(QKVW / 128, NROWS / 128), 256, GS_SMEM>>>(
        xh, wqh, nullptr, nullptr, qkv16, NROWS, QKVW, 1024);

    // 3) Fused pooling (fp16 planes)
    pool_fused<<<dim3(32, 32), 256>>>(qkv16);

    // 4) Block attention on tensor pipe
    attn_mma<<<2040, 256>>>(qkv16);

    // 5) Combine + normalize (-> fp16)
    combine_kernel<<<(NROWS * 128) / 256, 256>>>();

    // 6) Output projection (fp32 out + bias)
    gemm_fp16<0><<<dim3(1024 / 128, NROWS / 128), 256, GS_SMEM>>>(
        ath, woh, b_out, out, nullptr, NROWS, 1024, 512);
}

// round 10
// speedup vs baseline: 2.5862x; 1.0202x over previous
#include <cuda_runtime.h>
#include <cuda_fp16.h>
#include <cstdint>

// ---------------- Problem constants ----------------
#define NROWS   16384
#define QKVW    1536
#define POOLROWS 4064
#define YROWS    8160

// ---------------- Device scratch ----------------
__device__ __align__(16) __half g_Y[(size_t)32 * YROWS * 64];
__device__ __align__(16) float g_Asum[(size_t)32 * YROWS];

__device__ __align__(16) __half g_qkv16[(size_t)NROWS * QKVW];
__device__ __align__(16) __half g_poolq[(size_t)32 * POOLROWS * 64];
__device__ __align__(16) __half g_poolk[(size_t)32 * POOLROWS * 64];
__device__ __align__(16) __half g_poolv[(size_t)32 * POOLROWS * 64];

__device__ __align__(16) __half g_xh[(size_t)NROWS * 1024];
__device__ __align__(16) __half g_wqh[(size_t)QKVW * 1024];
__device__ __align__(16) __half g_woh[(size_t)1024 * 512];
__device__ __align__(16) __half g_atth[(size_t)NROWS * 512];

// ---------------- helpers ----------------
__device__ __forceinline__ uint32_t smem_to_u32(const void* p) {
    uint32_t a;
    asm("{ .reg .u64 t; cvta.to.shared.u64 t, %1; cvt.u32.u64 %0, t; }" : "=r"(a) : "l"(p));
    return a;
}
__device__ __forceinline__ uint32_t sw128(uint32_t off) {
    return off ^ ((off >> 3) & 0x70);
}

#define LDSM_X4(r0, r1, r2, r3, addr) \
    asm volatile("ldmatrix.sync.aligned.m8n8.x4.shared.b16 {%0,%1,%2,%3}, [%4];" \
        : "=r"(r0), "=r"(r1), "=r"(r2), "=r"(r3) : "r"(addr))
#define LDSM_X4_T(r0, r1, r2, r3, addr) \
    asm volatile("ldmatrix.sync.aligned.m8n8.x4.trans.shared.b16 {%0,%1,%2,%3}, [%4];" \
        : "=r"(r0), "=r"(r1), "=r"(r2), "=r"(r3) : "r"(addr))

__device__ __forceinline__ void mma16816h(float* c, const uint32_t* a, const uint32_t* b) {
    asm volatile(
        "mma.sync.aligned.m16n8k16.row.col.f32.f16.f16.f32 "
        "{%0,%1,%2,%3}, {%4,%5,%6,%7}, {%8,%9}, {%0,%1,%2,%3};"
        : "+f"(c[0]), "+f"(c[1]), "+f"(c[2]), "+f"(c[3])
        : "r"(a[0]), "r"(a[1]), "r"(a[2]), "r"(a[3]), "r"(b[0]), "r"(b[1]));
}

__device__ __forceinline__ uint2 cvt4h(float4 v) {
    uint2 r;
    __half2 lo = __floats2half2_rn(v.x, v.y);
    __half2 hi = __floats2half2_rn(v.z, v.w);
    r.x = *(uint32_t*)&lo;
    r.y = *(uint32_t*)&hi;
    return r;
}

// ---------------- one-shot fp32 -> fp16 conversion ----------------
__global__ __launch_bounds__(256)
void convert_all(const float* __restrict__ x, const float* __restrict__ wq,
                 const float* __restrict__ wo)
{
    int q = blockIdx.x * 256 + threadIdx.x;
    const float* src;
    uint2* dst;
    int local;
    if (q < 4194304) {
        src = x; dst = (uint2*)g_xh; local = q;
    } else if (q < 4194304 + 393216) {
        src = wq; dst = (uint2*)g_wqh; local = q - 4194304;
    } else {
        src = wo; dst = (uint2*)g_woh; local = q - 4194304 - 393216;
    }
    float4 v = *(const float4*)(src + (size_t)local * 4);
    dst[local] = cvt4h(v);
}

// ---------------- fp16 GEMM ------------------------------------------------
#define GS_STAGE 32768
#define GS_SMEM  (3 * GS_STAGE)

template <int OUT16>
__global__ __launch_bounds__(256, 2)
void gemm_fp16(const __half* __restrict__ A, const __half* __restrict__ B,
               const float* __restrict__ bias, float* __restrict__ C,
               __half* __restrict__ C16, int M, int N, int K)
{
    extern __shared__ __align__(1024) char smem[];
    const uint32_t smu = smem_to_u32(smem);
    const int tid = threadIdx.x;
    const int wid = tid >> 5, lane = tid & 31;
    const int warpM = wid & 1, warpN = wid >> 1;
    const int row0 = blockIdx.y * 128;
    const int col0 = blockIdx.x * 128;
    const int KS = K >> 6;

    float acc[4][4][4];
#pragma unroll
    for (int i = 0; i < 4; i++)
#pragma unroll
        for (int j = 0; j < 4; j++)
#pragma unroll
            for (int t = 0; t < 4; t++) acc[i][j][t] = 0.f;

    auto prefetch = [&](int ks, int buf) {
        uint32_t sb = smu + (uint32_t)buf * GS_STAGE;
        int q = tid & 7;
        int rbase = tid >> 3;
        const __half* pA = A + (size_t)row0 * K + ks * 64;
        const __half* pB = B + (size_t)col0 * K + ks * 64;
#pragma unroll
        for (int i = 0; i < 4; i++) {
            int r = (i << 5) + rbase;
            const void* gp = pA + (size_t)r * K + q * 8;
            uint32_t sa = sb + sw128((uint32_t)(r * 128 + q * 16));
            asm volatile("cp.async.cg.shared.global [%0], [%1], 16;" :: "r"(sa), "l"(gp));
        }
#pragma unroll
        for (int i = 0; i < 4; i++) {
            int r = (i << 5) + rbase;
            const void* gp = pB + (size_t)r * K + q * 8;
            uint32_t sa = sb + 16384 + sw128((uint32_t)(r * 128 + q * 16));
            asm volatile("cp.async.cg.shared.global [%0], [%1], 16;" :: "r"(sa), "l"(gp));
        }
    };

    auto compute_k16 = [&](uint32_t sbase, int kk) {
        uint32_t ah[4][4], bh[2][4];
        int aRow = warpM * 64 + (lane & 15);
        int aK2 = (kk * 16 + ((lane & 16) ? 8 : 0)) * 2;
#pragma unroll
        for (int mt = 0; mt < 4; mt++) {
            uint32_t off = sw128((uint32_t)((aRow + mt * 16) * 128 + aK2));
            LDSM_X4(ah[mt][0], ah[mt][1], ah[mt][2], ah[mt][3], sbase + off);
        }
        int bRow = warpN * 32 + (lane & 7) + ((lane & 16) ? 8 : 0);
        int bK2 = (kk * 16 + ((lane & 8) ? 8 : 0)) * 2;
#pragma unroll
        for (int pr = 0; pr < 2; pr++) {
            uint32_t off = sw128((uint32_t)((bRow + pr * 16) * 128 + bK2));
            LDSM_X4(bh[pr][0], bh[pr][1], bh[pr][2], bh[pr][3], sbase + 16384 + off);
        }
#pragma unroll
        for (int mt = 0; mt < 4; mt++)
#pragma unroll
            for (int nt = 0; nt < 4; nt++)
                mma16816h(acc[mt][nt], ah[mt], &bh[nt >> 1][(nt & 1) * 2]);
    };

    prefetch(0, 0);
    asm volatile("cp.async.commit_group;" ::: "memory");
    prefetch(1, 1);
    asm volatile("cp.async.commit_group;" ::: "memory");
    prefetch(2, 2);
    asm volatile("cp.async.commit_group;" ::: "memory");

    int buf = 0;
    for (int ks = 0; ks < KS; ks++) {
        asm volatile("cp.async.wait_group 2;" ::: "memory");
        __syncthreads();
        uint32_t sbase = smu + (uint32_t)buf * GS_STAGE;
#pragma unroll
        for (int kk = 0; kk < 4; kk++) compute_k16(sbase, kk);
        __syncthreads();
        if (ks + 3 < KS) prefetch(ks + 3, buf);
        asm volatile("cp.async.commit_group;" ::: "memory");
        buf = (buf + 1 == 3) ? 0 : buf + 1;
    }

    int mBase = row0 + warpM * 64 + (lane >> 2);
    int nBase = col0 + warpN * 32 + (lane & 3) * 2;
#pragma unroll
    for (int mt = 0; mt < 4; mt++)
#pragma unroll
        for (int nt = 0; nt < 4; nt++) {
            int m = mBase + mt * 16;
            int n = nBase + nt * 8;
            if (OUT16) {
                float s = (n < 512) ? 0.125f : 1.0f;
                __half2 h0 = __floats2half2_rn(acc[mt][nt][0] * s, acc[mt][nt][1] * s);
                __half2 h1 = __floats2half2_rn(acc[mt][nt][2] * s, acc[mt][nt][3] * s);
                *(__half2*)(C16 + (size_t)m * N + n) = h0;
                *(__half2*)(C16 + (size_t)(m + 8) * N + n) = h1;
            } else {
                float2 v0 = make_float2(acc[mt][nt][0], acc[mt][nt][1]);
                float2 v1 = make_float2(acc[mt][nt][2], acc[mt][nt][3]);
                float b0 = bias[n], b1 = bias[n + 1];
                v0.x += b0; v0.y += b1; v1.x += b0; v1.y += b1;
                *(float2*)(C + (size_t)m * N + n) = v0;
                *(float2*)(C + (size_t)(m + 8) * N + n) = v1;
            }
        }
}

// ---------------- Fused pooling (levels 1..7, fp16 in/out) ----------------
__global__ __launch_bounds__(256)
void pool_fused(const __half* __restrict__ qkv)
{
    __shared__ float sA[64][192];
    __shared__ float sB[32][192];

    int c  = blockIdx.x;
    int bh = blockIdx.y;
    int b = bh >> 3, h = bh & 7;
    int tid = threadIdx.x;
    int d = tid & 63, seg = tid >> 6;
    size_t poolbase = (size_t)bh * (POOLROWS * 64);

    for (int i = 0; i < 16; i++) {
        int li = seg * 16 + i;
        int grow = c * 128 + 2 * li;
        size_t base = ((size_t)(b * 4096 + grow)) * QKVW + h * 64 + d;
        float q = 0.5f * (__half2float(qkv[base]) + __half2float(qkv[base + QKVW]));
        float k = 0.5f * (__half2float(qkv[base + 512]) + __half2float(qkv[base + 512 + QKVW]));
        float v = __half2float(qkv[base + 1024]) + __half2float(qkv[base + 1024 + QKVW]);
        sA[li][d] = q; sA[li][64 + d] = k; sA[li][128 + d] = v;
        size_t dst = poolbase + (size_t)(c * 64 + li) * 64 + d;
        g_poolq[dst] = __float2half_rn(q);
        g_poolk[dst] = __float2half_rn(k);
        g_poolv[dst] = __float2half_rn(v);
    }
    __syncthreads();

    for (int l = 2; l <= 7; l++) {
        int nl = 64 >> (l - 1);
        int offL = 4096 - (8192 >> l);
        bool srcA = (l & 1) == 0;
        for (int idx = tid; idx < nl * 64; idx += 256) {
            int i = idx >> 6, dd = idx & 63;
            float q0, q1, k0, k1, v0, v1;
            if (srcA) {
                q0 = sA[2 * i][dd];       q1 = sA[2 * i + 1][dd];
                k0 = sA[2 * i][64 + dd];  k1 = sA[2 * i + 1][64 + dd];
                v0 = sA[2 * i][128 + dd]; v1 = sA[2 * i + 1][128 + dd];
            } else {
                q0 = sB[2 * i][dd];       q1 = sB[2 * i + 1][dd];
                k0 = sB[2 * i][64 + dd];  k1 = sB[2 * i + 1][64 + dd];
                v0 = sB[2 * i][128 + dd]; v1 = sB[2 * i + 1][128 + dd];
            }
            float q = 0.5f * (q0 + q1);
            float k = 0.5f * (k0 + k1);
            float v = v0 + v1;
            if (srcA) { sB[i][dd] = q; sB[i][64 + dd] = k; sB[i][128 + dd] = v; }
            else      { sA[i][dd] = q; sA[i][64 + dd] = k; sA[i][128 + dd] = v; }
            size_t dst = poolbase + (size_t)(offL + c * nl + i) * 64 + dd;
            g_poolq[dst] = __float2half_rn(q);
            g_poolk[dst] = __float2half_rn(k);
            g_poolv[dst] = __float2half_rn(v);
        }
        __syncthreads();
    }
}

// ---------------- Block attention via mma.sync -----------------------------
__global__ __launch_bounds__(256)
void attn_mma(const __half* __restrict__ qkv)
{
    __shared__ __align__(1024) char smem[8 * 6144];
    int warp = threadIdx.x >> 5;
    int lane = threadIdx.x & 31;
    int wg = blockIdx.x * 8 + warp;

    int bh = wg / 510;
    int r  = wg - bh * 510;
    int level = 0, nb = 256;
    while (r >= nb) { r -= nb; nb >>= 1; level++; }
    int blk = r;
    int b = bh >> 3, h = bh & 7;
    int kblk = (level == 0) ? blk : (blk ^ 1);

    char* st = smem + warp * 6144;
    const uint32_t su = smem_to_u32(st);

    const __half *qs, *ks, *vs;
    int stride;
    if (level == 0) {
        size_t rq = (size_t)(b * 4096 + blk * 16) * QKVW;
        size_t rk = (size_t)(b * 4096 + kblk * 16) * QKVW;
        qs = qkv + rq + h * 64;
        ks = qkv + rk + 512 + h * 64;
        vs = qkv + rq + 1024 + h * 64;
        stride = QKVW;
    } else {
        int off = 4096 - (8192 >> level);
        size_t pb = (size_t)bh * (POOLROWS * 64);
        qs = g_poolq + pb + (size_t)(off + blk * 16) * 64;
        ks = g_poolk + pb + (size_t)(off + kblk * 16) * 64;
        vs = g_poolv + pb + (size_t)(off + blk * 16) * 64;
        stride = 64;
    }

#pragma unroll
    for (int i = 0; i < 4; i++) {
        int chunk = i * 32 + lane;
        int row = chunk >> 3, qd = chunk & 7;
        uint32_t dst = sw128((uint32_t)(row * 128 + qd * 16));
        *(float4*)(st + dst)        = *(const float4*)(qs + (size_t)row * stride + qd * 8);
        *(float4*)(st + 2048 + dst) = *(const float4*)(ks + (size_t)row * stride + qd * 8);
        *(float4*)(st + 4096 + dst) = *(const float4*)(vs + (size_t)row * stride + qd * 8);
    }
    __syncwarp();

    // S = q k^T : M=16, N=16, K=64
    float s[2][4];
#pragma unroll
    for (int j = 0; j < 2; j++)
#pragma unroll
        for (int t = 0; t < 4; t++) s[j][t] = 0.f;

    int aRow = lane & 15;
    int bRow = (lane & 7) + ((lane & 16) ? 8 : 0);
#pragma unroll
    for (int kk = 0; kk < 4; kk++) {
        uint32_t ah[4], bh[4];
        uint32_t aoff = sw128((uint32_t)(aRow * 128 + (kk * 16 + ((lane & 16) ? 8 : 0)) * 2));
        LDSM_X4(ah[0], ah[1], ah[2], ah[3], su + aoff);
        uint32_t boff = sw128((uint32_t)(bRow * 128 + (kk * 16 + ((lane & 8) ? 8 : 0)) * 2));
        LDSM_X4(bh[0], bh[1], bh[2], bh[3], su + 2048 + boff);
        mma16816h(s[0], ah, &bh[0]);
        mma16816h(s[1], ah, &bh[2]);
    }

    // exp (fp32), quantize A to fp16; same quantized values feed asum.
    float e[2][4];
    uint32_t aA[4];
#pragma unroll
    for (int j = 0; j < 2; j++) {
#pragma unroll
        for (int t = 0; t < 4; t++) {
            __half hq = __float2half_rn(expf(s[j][t]));
            e[j][t] = __half2float(hq);
        }
        __half2 p0 = __floats2half2_rn(e[j][0], e[j][1]);
        __half2 p1 = __floats2half2_rn(e[j][2], e[j][3]);
        aA[j * 2 + 0] = *(uint32_t*)&p0;
        aA[j * 2 + 1] = *(uint32_t*)&p1;
    }
    uint32_t aF[4] = { aA[0], aA[1], aA[2], aA[3] };

    float sr  = e[0][0] + e[0][1] + e[1][0] + e[1][1];
    float sr8 = e[0][2] + e[0][3] + e[1][2] + e[1][3];
    sr  += __shfl_xor_sync(0xffffffffu, sr, 1);
    sr  += __shfl_xor_sync(0xffffffffu, sr, 2);
    sr8 += __shfl_xor_sync(0xffffffffu, sr8, 1);
    sr8 += __shfl_xor_sync(0xffffffffu, sr8, 2);

    // y = A v
    float y[8][4];
#pragma unroll
    for (int f = 0; f < 8; f++)
#pragma unroll
        for (int t = 0; t < 4; t++) y[f][t] = 0.f;

    int vRow = lane & 15;
    int vColBase = (lane & 16) ? 8 : 0;
#pragma unroll
    for (int vi = 0; vi < 4; vi++) {
        uint32_t vb[4];
        uint32_t voff = sw128((uint32_t)(vRow * 128 + (vColBase + vi * 16) * 2));
        LDSM_X4_T(vb[0], vb[1], vb[2], vb[3], su + 4096 + voff);
        mma16816h(y[vi * 2 + 0], aF, &vb[0]);
        mma16816h(y[vi * 2 + 1], aF, &vb[2]);
    }

    // Store Y (fp16 half2) and Asum (fp32)
    int yoff = 8192 - (8192 >> level);
    int r0 = lane >> 2;
    int c0 = (lane & 3) * 2;
    __half* Ybase = g_Y + (size_t)bh * (YROWS * 64) + (size_t)(yoff + blk * 16) * 64;
#pragma unroll
    for (int f = 0; f < 8; f++) {
        int d0 = f * 8 + c0;
        *(__half2*)(Ybase + (size_t)r0 * 64 + d0)       = __floats2half2_rn(y[f][0], y[f][1]);
        *(__half2*)(Ybase + (size_t)(r0 + 8) * 64 + d0) = __floats2half2_rn(y[f][2], y[f][3]);
    }
    if ((lane & 3) == 0) {
        float* Ab = g_Asum + (size_t)bh * YROWS + yoff + blk * 16;
        Ab[r0] = sr;
        Ab[r0 + 8] = sr8;
    }
}

// ---------------- Combine (fp16 Y in, fp16 att out) ----------------
__global__ __launch_bounds__(256)
void combine_kernel()
{
    int tid = blockIdx.x * 256 + threadIdx.x;
    int qd = tid & 127;                          // quad of 4 halves within row
    int m  = tid >> 7;
    int h  = qd >> 4, dq = qd & 15;
    int b = m >> 12, n = m & 4095;
    int bh = b * 8 + h;

    const __half* Yb = g_Y + (size_t)bh * (YROWS * 64);
    const float* Ab = g_Asum + (size_t)bh * YROWS;

    float4 ysum = make_float4(0.f, 0.f, 0.f, 0.f);
    float asum = 0.f;
#pragma unroll
    for (int l = 0; l < 8; l++) {
        int yoff = 8192 - (8192 >> l);
        int p = yoff + (n >> l);
        uint2 raw = ((const uint2*)(Yb + (size_t)p * 64))[dq];
        __half2 h0 = *(__half2*)&raw.x;
        __half2 h1 = *(__half2*)&raw.y;
        float2 f0 = __half22float2(h0);
        float2 f1 = __half22float2(h1);
        ysum.x += f0.x; ysum.y += f0.y; ysum.z += f1.x; ysum.w += f1.y;
        asum += Ab[p];
    }
    float inv = 1.f / (asum + 1e-8f);
    float4 val = make_float4(ysum.x * inv, ysum.y * inv, ysum.z * inv, ysum.w * inv);
    ((uint2*)g_atth)[tid] = cvt4h(val);
}

// ---------------- Launch ----------------
extern "C" void kernel_launch(void* const* d_in, const int* in_sizes, int n_in,
                              void* d_out, int out_size)
{
    const float* x     = (const float*)d_in[0];
    const float* w_qkv = (const float*)d_in[1];
    const float* w_out = (const float*)d_in[2];
    const float* b_out = (const float*)d_in[3];
    float* out = (float*)d_out;

    __half *xh, *wqh, *woh, *ath, *qkv16;
    cudaGetSymbolAddress((void**)&xh, g_xh);
    cudaGetSymbolAddress((void**)&wqh, g_wqh);
    cudaGetSymbolAddress((void**)&woh, g_woh);
    cudaGetSymbolAddress((void**)&ath, g_atth);
    cudaGetSymbolAddress((void**)&qkv16, g_qkv16);

    cudaFuncSetAttribute(gemm_fp16<0>, cudaFuncAttributeMaxDynamicSharedMemorySize, GS_SMEM);
    cudaFuncSetAttribute(gemm_fp16<1>, cudaFuncAttributeMaxDynamicSharedMemorySize, GS_SMEM);

    // 1) Convert inputs to fp16
    convert_all<<<18432, 256>>>(x, w_qkv, w_out);

    // 2) QKV projection -> fp16 qkv (q pre-scaled 0.125)
    gemm_fp16<1><<<dim3(QKVW / 128, NROWS / 128), 256, GS_SMEM>>>(
        xh, wqh, nullptr, nullptr, qkv16, NROWS, QKVW, 1024);

    // 3) Fused pooling (fp16 planes)
    pool_fused<<<dim3(32, 32), 256>>>(qkv16);

    // 4) Block attention on tensor pipe
    attn_mma<<<2040, 256>>>(qkv16);

    // 5) Combine + normalize (-> fp16)
    combine_kernel<<<(NROWS * 128) / 256, 256>>>();

    // 6) Output projection (fp32 out + bias)
    gemm_fp16<0><<<dim3(1024 / 128, NROWS / 128), 256, GS_SMEM>>>(
        ath, woh, b_out, out, nullptr, NROWS, 1024, 512);
}

// round 11
// speedup vs baseline: 2.6128x; 1.0103x over previous
#include <cuda_runtime.h>
#include <cuda_fp16.h>
#include <cstdint>

// ---------------- Problem constants ----------------
#define NROWS   16384
#define QKVW    1536
#define POOLROWS 4064     // coarse rows per bh (levels 1..7)

// ---------------- Device scratch ----------------
__device__ __align__(16) __half g_Yc[(size_t)32 * POOLROWS * 64];   // coarse Y (levels 1..7)
__device__ __align__(16) float  g_Ac[(size_t)32 * POOLROWS];        // coarse Asum
__device__ __align__(16) float  g_YC[(size_t)32 * 2048 * 64];       // collapsed coarse prefix
__device__ __align__(16) float  g_AC[(size_t)32 * 2048];

__device__ __align__(16) __half g_qkv16[(size_t)NROWS * QKVW];
__device__ __align__(16) __half g_poolq[(size_t)32 * POOLROWS * 64];
__device__ __align__(16) __half g_poolk[(size_t)32 * POOLROWS * 64];
__device__ __align__(16) __half g_poolv[(size_t)32 * POOLROWS * 64];

__device__ __align__(16) __half g_xh[(size_t)NROWS * 1024];
__device__ __align__(16) __half g_wqh[(size_t)QKVW * 1024];
__device__ __align__(16) __half g_woh[(size_t)1024 * 512];
__device__ __align__(16) __half g_atth[(size_t)NROWS * 512];

// ---------------- helpers ----------------
__device__ __forceinline__ uint32_t smem_to_u32(const void* p) {
    uint32_t a;
    asm("{ .reg .u64 t; cvta.to.shared.u64 t, %1; cvt.u32.u64 %0, t; }" : "=r"(a) : "l"(p));
    return a;
}
__device__ __forceinline__ uint32_t sw128(uint32_t off) {
    return off ^ ((off >> 3) & 0x70);
}

#define LDSM_X4(r0, r1, r2, r3, addr) \
    asm volatile("ldmatrix.sync.aligned.m8n8.x4.shared.b16 {%0,%1,%2,%3}, [%4];" \
        : "=r"(r0), "=r"(r1), "=r"(r2), "=r"(r3) : "r"(addr))
#define LDSM_X4_T(r0, r1, r2, r3, addr) \
    asm volatile("ldmatrix.sync.aligned.m8n8.x4.trans.shared.b16 {%0,%1,%2,%3}, [%4];" \
        : "=r"(r0), "=r"(r1), "=r"(r2), "=r"(r3) : "r"(addr))

__device__ __forceinline__ void mma16816h(float* c, const uint32_t* a, const uint32_t* b) {
    asm volatile(
        "mma.sync.aligned.m16n8k16.row.col.f32.f16.f16.f32 "
        "{%0,%1,%2,%3}, {%4,%5,%6,%7}, {%8,%9}, {%0,%1,%2,%3};"
        : "+f"(c[0]), "+f"(c[1]), "+f"(c[2]), "+f"(c[3])
        : "r"(a[0]), "r"(a[1]), "r"(a[2]), "r"(a[3]), "r"(b[0]), "r"(b[1]));
}

__device__ __forceinline__ uint2 cvt4h(float4 v) {
    uint2 r;
    __half2 lo = __floats2half2_rn(v.x, v.y);
    __half2 hi = __floats2half2_rn(v.z, v.w);
    r.x = *(uint32_t*)&lo;
    r.y = *(uint32_t*)&hi;
    return r;
}

// ---------------- one-shot fp32 -> fp16 conversion ----------------
__global__ __launch_bounds__(256)
void convert_all(const float* __restrict__ x, const float* __restrict__ wq,
                 const float* __restrict__ wo)
{
    int q = blockIdx.x * 256 + threadIdx.x;
    const float* src;
    uint2* dst;
    int local;
    if (q < 4194304) {
        src = x; dst = (uint2*)g_xh; local = q;
    } else if (q < 4194304 + 393216) {
        src = wq; dst = (uint2*)g_wqh; local = q - 4194304;
    } else {
        src = wo; dst = (uint2*)g_woh; local = q - 4194304 - 393216;
    }
    float4 v = *(const float4*)(src + (size_t)local * 4);
    dst[local] = cvt4h(v);
}

// ---------------- fp16 GEMM ------------------------------------------------
#define GS_STAGE 32768
#define GS_SMEM  (3 * GS_STAGE)

template <int OUT16>
__global__ __launch_bounds__(256, 2)
void gemm_fp16(const __half* __restrict__ A, const __half* __restrict__ B,
               const float* __restrict__ bias, float* __restrict__ C,
               __half* __restrict__ C16, int M, int N, int K)
{
    extern __shared__ __align__(1024) char smem[];
    const uint32_t smu = smem_to_u32(smem);
    const int tid = threadIdx.x;
    const int wid = tid >> 5, lane = tid & 31;
    const int warpM = wid & 1, warpN = wid >> 1;
    const int row0 = blockIdx.y * 128;
    const int col0 = blockIdx.x * 128;
    const int KS = K >> 6;

    float acc[4][4][4];
#pragma unroll
    for (int i = 0; i < 4; i++)
#pragma unroll
        for (int j = 0; j < 4; j++)
#pragma unroll
            for (int t = 0; t < 4; t++) acc[i][j][t] = 0.f;

    auto prefetch = [&](int ks, int buf) {
        uint32_t sb = smu + (uint32_t)buf * GS_STAGE;
        int q = tid & 7;
        int rbase = tid >> 3;
        const __half* pA = A + (size_t)row0 * K + ks * 64;
        const __half* pB = B + (size_t)col0 * K + ks * 64;
#pragma unroll
        for (int i = 0; i < 4; i++) {
            int r = (i << 5) + rbase;
            const void* gp = pA + (size_t)r * K + q * 8;
            uint32_t sa = sb + sw128((uint32_t)(r * 128 + q * 16));
            asm volatile("cp.async.cg.shared.global [%0], [%1], 16;" :: "r"(sa), "l"(gp));
        }
#pragma unroll
        for (int i = 0; i < 4; i++) {
            int r = (i << 5) + rbase;
            const void* gp = pB + (size_t)r * K + q * 8;
            uint32_t sa = sb + 16384 + sw128((uint32_t)(r * 128 + q * 16));
            asm volatile("cp.async.cg.shared.global [%0], [%1], 16;" :: "r"(sa), "l"(gp));
        }
    };

    auto compute_k16 = [&](uint32_t sbase, int kk) {
        uint32_t ah[4][4], bh[2][4];
        int aRow = warpM * 64 + (lane & 15);
        int aK2 = (kk * 16 + ((lane & 16) ? 8 : 0)) * 2;
#pragma unroll
        for (int mt = 0; mt < 4; mt++) {
            uint32_t off = sw128((uint32_t)((aRow + mt * 16) * 128 + aK2));
            LDSM_X4(ah[mt][0], ah[mt][1], ah[mt][2], ah[mt][3], sbase + off);
        }
        int bRow = warpN * 32 + (lane & 7) + ((lane & 16) ? 8 : 0);
        int bK2 = (kk * 16 + ((lane & 8) ? 8 : 0)) * 2;
#pragma unroll
        for (int pr = 0; pr < 2; pr++) {
            uint32_t off = sw128((uint32_t)((bRow + pr * 16) * 128 + bK2));
            LDSM_X4(bh[pr][0], bh[pr][1], bh[pr][2], bh[pr][3], sbase + 16384 + off);
        }
#pragma unroll
        for (int mt = 0; mt < 4; mt++)
#pragma unroll
            for (int nt = 0; nt < 4; nt++)
                mma16816h(acc[mt][nt], ah[mt], &bh[nt >> 1][(nt & 1) * 2]);
    };

    prefetch(0, 0);
    asm volatile("cp.async.commit_group;" ::: "memory");
    prefetch(1, 1);
    asm volatile("cp.async.commit_group;" ::: "memory");
    prefetch(2, 2);
    asm volatile("cp.async.commit_group;" ::: "memory");

    int buf = 0;
    for (int ks = 0; ks < KS; ks++) {
        asm volatile("cp.async.wait_group 2;" ::: "memory");
        __syncthreads();
        uint32_t sbase = smu + (uint32_t)buf * GS_STAGE;
#pragma unroll
        for (int kk = 0; kk < 4; kk++) compute_k16(sbase, kk);
        __syncthreads();
        if (ks + 3 < KS) prefetch(ks + 3, buf);
        asm volatile("cp.async.commit_group;" ::: "memory");
        buf = (buf + 1 == 3) ? 0 : buf + 1;
    }

    int mBase = row0 + warpM * 64 + (lane >> 2);
    int nBase = col0 + warpN * 32 + (lane & 3) * 2;
#pragma unroll
    for (int mt = 0; mt < 4; mt++)
#pragma unroll
        for (int nt = 0; nt < 4; nt++) {
            int m = mBase + mt * 16;
            int n = nBase + nt * 8;
            if (OUT16) {
                float s = (n < 512) ? 0.125f : 1.0f;
                __half2 h0 = __floats2half2_rn(acc[mt][nt][0] * s, acc[mt][nt][1] * s);
                __half2 h1 = __floats2half2_rn(acc[mt][nt][2] * s, acc[mt][nt][3] * s);
                *(__half2*)(C16 + (size_t)m * N + n) = h0;
                *(__half2*)(C16 + (size_t)(m + 8) * N + n) = h1;
            } else {
                float2 v0 = make_float2(acc[mt][nt][0], acc[mt][nt][1]);
                float2 v1 = make_float2(acc[mt][nt][2], acc[mt][nt][3]);
                float b0 = bias[n], b1 = bias[n + 1];
                v0.x += b0; v0.y += b1; v1.x += b0; v1.y += b1;
                *(float2*)(C + (size_t)m * N + n) = v0;
                *(float2*)(C + (size_t)(m + 8) * N + n) = v1;
            }
        }
}

// ---------------- Fused pooling (levels 1..7, fp16 in/out) ----------------
__global__ __launch_bounds__(256)
void pool_fused(const __half* __restrict__ qkv)
{
    __shared__ float sA[64][192];
    __shared__ float sB[32][192];

    int c  = blockIdx.x;
    int bh = blockIdx.y;
    int b = bh >> 3, h = bh & 7;
    int tid = threadIdx.x;
    int d = tid & 63, seg = tid >> 6;
    size_t poolbase = (size_t)bh * (POOLROWS * 64);

    for (int i = 0; i < 16; i++) {
        int li = seg * 16 + i;
        int grow = c * 128 + 2 * li;
        size_t base = ((size_t)(b * 4096 + grow)) * QKVW + h * 64 + d;
        float q = 0.5f * (__half2float(qkv[base]) + __half2float(qkv[base + QKVW]));
        float k = 0.5f * (__half2float(qkv[base + 512]) + __half2float(qkv[base + 512 + QKVW]));
        float v = __half2float(qkv[base + 1024]) + __half2float(qkv[base + 1024 + QKVW]);
        sA[li][d] = q; sA[li][64 + d] = k; sA[li][128 + d] = v;
        size_t dst = poolbase + (size_t)(c * 64 + li) * 64 + d;
        g_poolq[dst] = __float2half_rn(q);
        g_poolk[dst] = __float2half_rn(k);
        g_poolv[dst] = __float2half_rn(v);
    }
    __syncthreads();

    for (int l = 2; l <= 7; l++) {
        int nl = 64 >> (l - 1);
        int offL = 4096 - (8192 >> l);
        bool srcA = (l & 1) == 0;
        for (int idx = tid; idx < nl * 64; idx += 256) {
            int i = idx >> 6, dd = idx & 63;
            float q0, q1, k0, k1, v0, v1;
            if (srcA) {
                q0 = sA[2 * i][dd];       q1 = sA[2 * i + 1][dd];
                k0 = sA[2 * i][64 + dd];  k1 = sA[2 * i + 1][64 + dd];
                v0 = sA[2 * i][128 + dd]; v1 = sA[2 * i + 1][128 + dd];
            } else {
                q0 = sB[2 * i][dd];       q1 = sB[2 * i + 1][dd];
                k0 = sB[2 * i][64 + dd];  k1 = sB[2 * i + 1][64 + dd];
                v0 = sB[2 * i][128 + dd]; v1 = sB[2 * i + 1][128 + dd];
            }
            float q = 0.5f * (q0 + q1);
            float k = 0.5f * (k0 + k1);
            float v = v0 + v1;
            if (srcA) { sB[i][dd] = q; sB[i][64 + dd] = k; sB[i][128 + dd] = v; }
            else      { sA[i][dd] = q; sA[i][64 + dd] = k; sA[i][128 + dd] = v; }
            size_t dst = poolbase + (size_t)(offL + c * nl + i) * 64 + dd;
            g_poolq[dst] = __float2half_rn(q);
            g_poolk[dst] = __float2half_rn(k);
            g_poolv[dst] = __float2half_rn(v);
        }
        __syncthreads();
    }
}

// ---------------- Shared attention core (per-warp 16x16 block) -------------
struct AttnOut {
    float y[8][4];
    float sr, sr8;
};

__device__ __forceinline__ void attn_block_core(
    const __half* qs, const __half* ks, const __half* vs, int stride,
    char* st, uint32_t su, int lane, AttnOut& o)
{
#pragma unroll
    for (int i = 0; i < 4; i++) {
        int chunk = i * 32 + lane;
        int row = chunk >> 3, qd = chunk & 7;
        uint32_t dst = sw128((uint32_t)(row * 128 + qd * 16));
        *(float4*)(st + dst)        = *(const float4*)(qs + (size_t)row * stride + qd * 8);
        *(float4*)(st + 2048 + dst) = *(const float4*)(ks + (size_t)row * stride + qd * 8);
        *(float4*)(st + 4096 + dst) = *(const float4*)(vs + (size_t)row * stride + qd * 8);
    }
    __syncwarp();

    float s[2][4];
#pragma unroll
    for (int j = 0; j < 2; j++)
#pragma unroll
        for (int t = 0; t < 4; t++) s[j][t] = 0.f;

    int aRow = lane & 15;
    int bRow = (lane & 7) + ((lane & 16) ? 8 : 0);
#pragma unroll
    for (int kk = 0; kk < 4; kk++) {
        uint32_t ah[4], bh[4];
        uint32_t aoff = sw128((uint32_t)(aRow * 128 + (kk * 16 + ((lane & 16) ? 8 : 0)) * 2));
        LDSM_X4(ah[0], ah[1], ah[2], ah[3], su + aoff);
        uint32_t boff = sw128((uint32_t)(bRow * 128 + (kk * 16 + ((lane & 8) ? 8 : 0)) * 2));
        LDSM_X4(bh[0], bh[1], bh[2], bh[3], su + 2048 + boff);
        mma16816h(s[0], ah, &bh[0]);
        mma16816h(s[1], ah, &bh[2]);
    }

    float e[2][4];
    uint32_t aF[4];
#pragma unroll
    for (int j = 0; j < 2; j++) {
#pragma unroll
        for (int t = 0; t < 4; t++) {
            __half hq = __float2half_rn(expf(s[j][t]));
            e[j][t] = __half2float(hq);
        }
        __half2 p0 = __floats2half2_rn(e[j][0], e[j][1]);
        __half2 p1 = __floats2half2_rn(e[j][2], e[j][3]);
        aF[j * 2 + 0] = *(uint32_t*)&p0;
        aF[j * 2 + 1] = *(uint32_t*)&p1;
    }

    float sr  = e[0][0] + e[0][1] + e[1][0] + e[1][1];
    float sr8 = e[0][2] + e[0][3] + e[1][2] + e[1][3];
    sr  += __shfl_xor_sync(0xffffffffu, sr, 1);
    sr  += __shfl_xor_sync(0xffffffffu, sr, 2);
    sr8 += __shfl_xor_sync(0xffffffffu, sr8, 1);
    sr8 += __shfl_xor_sync(0xffffffffu, sr8, 2);
    o.sr = sr; o.sr8 = sr8;

#pragma unroll
    for (int f = 0; f < 8; f++)
#pragma unroll
        for (int t = 0; t < 4; t++) o.y[f][t] = 0.f;

    int vRow = lane & 15;
    int vColBase = (lane & 16) ? 8 : 0;
#pragma unroll
    for (int vi = 0; vi < 4; vi++) {
        uint32_t vb[4];
        uint32_t voff = sw128((uint32_t)(vRow * 128 + (vColBase + vi * 16) * 2));
        LDSM_X4_T(vb[0], vb[1], vb[2], vb[3], su + 4096 + voff);
        mma16816h(o.y[vi * 2 + 0], aF, &vb[0]);
        mma16816h(o.y[vi * 2 + 1], aF, &vb[2]);
    }
}

// ---------------- attn over coarse levels (1..7) ---------------------------
__global__ __launch_bounds__(256)
void attn_coarse()
{
    __shared__ __align__(1024) char smem[8 * 6144];
    int warp = threadIdx.x >> 5;
    int lane = threadIdx.x & 31;
    int wg = blockIdx.x * 8 + warp;            // [0, 8128)

    int bh = wg / 254;
    int r  = wg - bh * 254;
    int level = 1, nb = 128;
    while (r >= nb) { r -= nb; nb >>= 1; level++; }
    int blk = r;
    int kblk = blk ^ 1;

    char* st = smem + warp * 6144;
    const uint32_t su = smem_to_u32(st);

    int off = 4096 - (8192 >> level);
    size_t pb = (size_t)bh * (POOLROWS * 64);
    const __half* qs = g_poolq + pb + (size_t)(off + blk * 16) * 64;
    const __half* ks = g_poolk + pb + (size_t)(off + kblk * 16) * 64;
    const __half* vs = g_poolv + pb + (size_t)(off + blk * 16) * 64;

    AttnOut o;
    attn_block_core(qs, ks, vs, 64, st, su, lane, o);

    int r0 = lane >> 2;
    int c0 = (lane & 3) * 2;
    __half* Ybase = g_Yc + pb + (size_t)(off + blk * 16) * 64;
#pragma unroll
    for (int f = 0; f < 8; f++) {
        int d0 = f * 8 + c0;
        *(__half2*)(Ybase + (size_t)r0 * 64 + d0)       = __floats2half2_rn(o.y[f][0], o.y[f][1]);
        *(__half2*)(Ybase + (size_t)(r0 + 8) * 64 + d0) = __floats2half2_rn(o.y[f][2], o.y[f][3]);
    }
    if ((lane & 3) == 0) {
        float* Ab = g_Ac + (size_t)bh * POOLROWS + off + blk * 16;
        Ab[r0] = o.sr;
        Ab[r0 + 8] = o.sr8;
    }
}

// ---------------- collapse coarse levels to level-1 prefix -----------------
// YC[n1] = sum_{l=1..7} Yc_l[n1 >> (l-1)],  AC likewise.
__global__ __launch_bounds__(256)
void accum_coarse()
{
    int tid = blockIdx.x * 256 + threadIdx.x;   // 32*2048*16
    int d4 = tid & 15;
    int n1 = (tid >> 4) & 2047;
    int bh = tid >> 15;

    const __half* Yb = g_Yc + (size_t)bh * (POOLROWS * 64);
    const float* Ab = g_Ac + (size_t)bh * POOLROWS;

    float4 acc = make_float4(0.f, 0.f, 0.f, 0.f);
    float asum = 0.f;
#pragma unroll
    for (int l = 1; l <= 7; l++) {
        int p = (4096 - (8192 >> l)) + (n1 >> (l - 1));
        uint2 raw = ((const uint2*)(Yb + (size_t)p * 64))[d4];
        float2 f0 = __half22float2(*(__half2*)&raw.x);
        float2 f1 = __half22float2(*(__half2*)&raw.y);
        acc.x += f0.x; acc.y += f0.y; acc.z += f1.x; acc.w += f1.y;
        asum += Ab[p];
    }
    ((float4*)(g_YC + (size_t)bh * (2048 * 64)))[(size_t)n1 * 16 + d4] = acc;
    if (d4 == 0) g_AC[(size_t)bh * 2048 + n1] = asum;
}

// ---------------- level-0 attention fused with combine ---------------------
__global__ __launch_bounds__(256)
void attn0_combine(const __half* __restrict__ qkv)
{
    __shared__ __align__(1024) char smem[8 * 6144];
    int warp = threadIdx.x >> 5;
    int lane = threadIdx.x & 31;
    int wg = blockIdx.x * 8 + warp;            // [0, 8192)

    int bh = wg >> 8;
    int blk = wg & 255;
    int b = bh >> 3, h = bh & 7;

    char* st = smem + warp * 6144;
    const uint32_t su = smem_to_u32(st);

    size_t rq = (size_t)(b * 4096 + blk * 16) * QKVW;
    const __half* qs = qkv + rq + h * 64;
    const __half* ks = qkv + rq + 512 + h * 64;
    const __half* vs = qkv + rq + 1024 + h * 64;

    AttnOut o;
    attn_block_core(qs, ks, vs, QKVW, st, su, lane, o);

    // Combine with coarse prefix and emit fp16 att directly.
    int n0 = blk * 16;
    int r0 = lane >> 2;
    int c0 = (lane & 3) * 2;

    const float* YCb = g_YC + (size_t)bh * (2048 * 64);
    const float* ACb = g_AC + (size_t)bh * 2048;
    int p_r  = (n0 + r0) >> 1;
    int p_r8 = (n0 + r0 + 8) >> 1;
    float invA_r  = 1.f / (o.sr  + ACb[p_r]  + 1e-8f);
    float invA_r8 = 1.f / (o.sr8 + ACb[p_r8] + 1e-8f);

    __half* att_r  = g_atth + (size_t)(b * 4096 + n0 + r0) * 512 + h * 64;
    __half* att_r8 = g_atth + (size_t)(b * 4096 + n0 + r0 + 8) * 512 + h * 64;
    const float* yc_r  = YCb + (size_t)p_r * 64;
    const float* yc_r8 = YCb + (size_t)p_r8 * 64;
#pragma unroll
    for (int f = 0; f < 8; f++) {
        int d0 = f * 8 + c0;
        float2 c_r  = *(const float2*)(yc_r + d0);
        float2 c_r8 = *(const float2*)(yc_r8 + d0);
        *(__half2*)(att_r + d0)  = __floats2half2_rn((o.y[f][0] + c_r.x) * invA_r,
                                                     (o.y[f][1] + c_r.y) * invA_r);
        *(__half2*)(att_r8 + d0) = __floats2half2_rn((o.y[f][2] + c_r8.x) * invA_r8,
                                                     (o.y[f][3] + c_r8.y) * invA_r8);
    }
}

// ---------------- Launch ----------------
extern "C" void kernel_launch(void* const* d_in, const int* in_sizes, int n_in,
                              void* d_out, int out_size)
{
    const float* x     = (const float*)d_in[0];
    const float* w_qkv = (const float*)d_in[1];
    const float* w_out = (const float*)d_in[2];
    const float* b_out = (const float*)d_in[3];
    float* out = (float*)d_out;

    __half *xh, *wqh, *woh, *ath, *qkv16;
    cudaGetSymbolAddress((void**)&xh, g_xh);
    cudaGetSymbolAddress((void**)&wqh, g_wqh);
    cudaGetSymbolAddress((void**)&woh, g_woh);
    cudaGetSymbolAddress((void**)&ath, g_atth);
    cudaGetSymbolAddress((void**)&qkv16, g_qkv16);

    cudaFuncSetAttribute(gemm_fp16<0>, cudaFuncAttributeMaxDynamicSharedMemorySize, GS_SMEM);
    cudaFuncSetAttribute(gemm_fp16<1>, cudaFuncAttributeMaxDynamicSharedMemorySize, GS_SMEM);

    // 1) Convert inputs to fp16
    convert_all<<<18432, 256>>>(x, w_qkv, w_out);

    // 2) QKV projection -> fp16 qkv (q pre-scaled 0.125)
    gemm_fp16<1><<<dim3(QKVW / 128, NROWS / 128), 256, GS_SMEM>>>(
        xh, wqh, nullptr, nullptr, qkv16, NROWS, QKVW, 1024);

    // 3) Fused pooling (fp16 planes)
    pool_fused<<<dim3(32, 32), 256>>>(qkv16);

    // 4) Coarse attention (levels 1..7): 32*254 warps
    attn_coarse<<<1016, 256>>>();

    // 5) Collapse coarse levels into level-1 prefix YC/AC
    accum_coarse<<<4096, 256>>>();

    // 6) Level-0 attention + combine -> fp16 att
    attn0_combine<<<1024, 256>>>(qkv16);

    // 7) Output projection (fp32 out + bias)
    gemm_fp16<0><<<dim3(1024 / 128, NROWS / 128), 256, GS_SMEM>>>(
        ath, woh, b_out, out, nullptr, NROWS, 1024, 512);
}

// round 12
// speedup vs baseline: 2.6721x; 1.0227x over previous
#include <cuda_runtime.h>
#include <cuda_fp16.h>
#include <cstdint>

// ---------------- Problem constants ----------------
#define NROWS   16384
#define QKVW    1536
#define POOLROWS 4064     // coarse rows per bh (levels 1..7)

// ---------------- Device scratch ----------------
__device__ __align__(16) __half g_Yc[(size_t)32 * POOLROWS * 64];   // coarse Y (levels 1..7)
__device__ __align__(16) float  g_Ac[(size_t)32 * POOLROWS];        // coarse Asum

__device__ __align__(16) __half g_qkv16[(size_t)NROWS * QKVW];
__device__ __align__(16) __half g_poolq[(size_t)32 * POOLROWS * 64];
__device__ __align__(16) __half g_poolk[(size_t)32 * POOLROWS * 64];
__device__ __align__(16) __half g_poolv[(size_t)32 * POOLROWS * 64];

__device__ __align__(16) __half g_xh[(size_t)NROWS * 1024];
__device__ __align__(16) __half g_wqh[(size_t)QKVW * 1024];
__device__ __align__(16) __half g_woh[(size_t)1024 * 512];
__device__ __align__(16) __half g_atth[(size_t)NROWS * 512];

// ---------------- helpers ----------------
__device__ __forceinline__ uint32_t smem_to_u32(const void* p) {
    uint32_t a;
    asm("{ .reg .u64 t; cvta.to.shared.u64 t, %1; cvt.u32.u64 %0, t; }" : "=r"(a) : "l"(p));
    return a;
}
__device__ __forceinline__ uint32_t sw128(uint32_t off) {
    return off ^ ((off >> 3) & 0x70);
}

#define LDSM_X4(r0, r1, r2, r3, addr) \
    asm volatile("ldmatrix.sync.aligned.m8n8.x4.shared.b16 {%0,%1,%2,%3}, [%4];" \
        : "=r"(r0), "=r"(r1), "=r"(r2), "=r"(r3) : "r"(addr))
#define LDSM_X4_T(r0, r1, r2, r3, addr) \
    asm volatile("ldmatrix.sync.aligned.m8n8.x4.trans.shared.b16 {%0,%1,%2,%3}, [%4];" \
        : "=r"(r0), "=r"(r1), "=r"(r2), "=r"(r3) : "r"(addr))

__device__ __forceinline__ void mma16816h(float* c, const uint32_t* a, const uint32_t* b) {
    asm volatile(
        "mma.sync.aligned.m16n8k16.row.col.f32.f16.f16.f32 "
        "{%0,%1,%2,%3}, {%4,%5,%6,%7}, {%8,%9}, {%0,%1,%2,%3};"
        : "+f"(c[0]), "+f"(c[1]), "+f"(c[2]), "+f"(c[3])
        : "r"(a[0]), "r"(a[1]), "r"(a[2]), "r"(a[3]), "r"(b[0]), "r"(b[1]));
}

__device__ __forceinline__ uint2 cvt4h(float4 v) {
    uint2 r;
    __half2 lo = __floats2half2_rn(v.x, v.y);
    __half2 hi = __floats2half2_rn(v.z, v.w);
    r.x = *(uint32_t*)&lo;
    r.y = *(uint32_t*)&hi;
    return r;
}

// ---------------- one-shot fp32 -> fp16 conversion ----------------
__global__ __launch_bounds__(256)
void convert_all(const float* __restrict__ x, const float* __restrict__ wq,
                 const float* __restrict__ wo)
{
    int q = blockIdx.x * 256 + threadIdx.x;
    const float* src;
    uint2* dst;
    int local;
    if (q < 4194304) {
        src = x; dst = (uint2*)g_xh; local = q;
    } else if (q < 4194304 + 393216) {
        src = wq; dst = (uint2*)g_wqh; local = q - 4194304;
    } else {
        src = wo; dst = (uint2*)g_woh; local = q - 4194304 - 393216;
    }
    float4 v = *(const float4*)(src + (size_t)local * 4);
    dst[local] = cvt4h(v);
}

// ---------------- fp16 GEMM ------------------------------------------------
#define GS_STAGE 32768
#define GS_SMEM  (3 * GS_STAGE)

template <int OUT16>
__global__ __launch_bounds__(256, 2)
void gemm_fp16(const __half* __restrict__ A, const __half* __restrict__ B,
               const float* __restrict__ bias, float* __restrict__ C,
               __half* __restrict__ C16, int M, int N, int K)
{
    extern __shared__ __align__(1024) char smem[];
    const uint32_t smu = smem_to_u32(smem);
    const int tid = threadIdx.x;
    const int wid = tid >> 5, lane = tid & 31;
    const int warpM = wid & 1, warpN = wid >> 1;
    const int row0 = blockIdx.y * 128;
    const int col0 = blockIdx.x * 128;
    const int KS = K >> 6;

    float acc[4][4][4];
#pragma unroll
    for (int i = 0; i < 4; i++)
#pragma unroll
        for (int j = 0; j < 4; j++)
#pragma unroll
            for (int t = 0; t < 4; t++) acc[i][j][t] = 0.f;

    auto prefetch = [&](int ks, int buf) {
        uint32_t sb = smu + (uint32_t)buf * GS_STAGE;
        int q = tid & 7;
        int rbase = tid >> 3;
        const __half* pA = A + (size_t)row0 * K + ks * 64;
        const __half* pB = B + (size_t)col0 * K + ks * 64;
#pragma unroll
        for (int i = 0; i < 4; i++) {
            int r = (i << 5) + rbase;
            const void* gp = pA + (size_t)r * K + q * 8;
            uint32_t sa = sb + sw128((uint32_t)(r * 128 + q * 16));
            asm volatile("cp.async.cg.shared.global [%0], [%1], 16;" :: "r"(sa), "l"(gp));
        }
#pragma unroll
        for (int i = 0; i < 4; i++) {
            int r = (i << 5) + rbase;
            const void* gp = pB + (size_t)r * K + q * 8;
            uint32_t sa = sb + 16384 + sw128((uint32_t)(r * 128 + q * 16));
            asm volatile("cp.async.cg.shared.global [%0], [%1], 16;" :: "r"(sa), "l"(gp));
        }
    };

    auto compute_k16 = [&](uint32_t sbase, int kk) {
        uint32_t ah[4][4], bh[2][4];
        int aRow = warpM * 64 + (lane & 15);
        int aK2 = (kk * 16 + ((lane & 16) ? 8 : 0)) * 2;
#pragma unroll
        for (int mt = 0; mt < 4; mt++) {
            uint32_t off = sw128((uint32_t)((aRow + mt * 16) * 128 + aK2));
            LDSM_X4(ah[mt][0], ah[mt][1], ah[mt][2], ah[mt][3], sbase + off);
        }
        int bRow = warpN * 32 + (lane & 7) + ((lane & 16) ? 8 : 0);
        int bK2 = (kk * 16 + ((lane & 8) ? 8 : 0)) * 2;
#pragma unroll
        for (int pr = 0; pr < 2; pr++) {
            uint32_t off = sw128((uint32_t)((bRow + pr * 16) * 128 + bK2));
            LDSM_X4(bh[pr][0], bh[pr][1], bh[pr][2], bh[pr][3], sbase + 16384 + off);
        }
#pragma unroll
        for (int mt = 0; mt < 4; mt++)
#pragma unroll
            for (int nt = 0; nt < 4; nt++)
                mma16816h(acc[mt][nt], ah[mt], &bh[nt >> 1][(nt & 1) * 2]);
    };

    prefetch(0, 0);
    asm volatile("cp.async.commit_group;" ::: "memory");
    prefetch(1, 1);
    asm volatile("cp.async.commit_group;" ::: "memory");
    prefetch(2, 2);
    asm volatile("cp.async.commit_group;" ::: "memory");

    int buf = 0;
    for (int ks = 0; ks < KS; ks++) {
        asm volatile("cp.async.wait_group 2;" ::: "memory");
        __syncthreads();
        uint32_t sbase = smu + (uint32_t)buf * GS_STAGE;
#pragma unroll
        for (int kk = 0; kk < 4; kk++) compute_k16(sbase, kk);
        __syncthreads();
        if (ks + 3 < KS) prefetch(ks + 3, buf);
        asm volatile("cp.async.commit_group;" ::: "memory");
        buf = (buf + 1 == 3) ? 0 : buf + 1;
    }

    int mBase = row0 + warpM * 64 + (lane >> 2);
    int nBase = col0 + warpN * 32 + (lane & 3) * 2;
#pragma unroll
    for (int mt = 0; mt < 4; mt++)
#pragma unroll
        for (int nt = 0; nt < 4; nt++) {
            int m = mBase + mt * 16;
            int n = nBase + nt * 8;
            if (OUT16) {
                float s = (n < 512) ? 0.125f : 1.0f;
                __half2 h0 = __floats2half2_rn(acc[mt][nt][0] * s, acc[mt][nt][1] * s);
                __half2 h1 = __floats2half2_rn(acc[mt][nt][2] * s, acc[mt][nt][3] * s);
                *(__half2*)(C16 + (size_t)m * N + n) = h0;
                *(__half2*)(C16 + (size_t)(m + 8) * N + n) = h1;
            } else {
                float2 v0 = make_float2(acc[mt][nt][0], acc[mt][nt][1]);
                float2 v1 = make_float2(acc[mt][nt][2], acc[mt][nt][3]);
                float b0 = bias[n], b1 = bias[n + 1];
                v0.x += b0; v0.y += b1; v1.x += b0; v1.y += b1;
                *(float2*)(C + (size_t)m * N + n) = v0;
                *(float2*)(C + (size_t)(m + 8) * N + n) = v1;
            }
        }
}

// ---------------- Fused pooling (levels 1..7, fp16 in/out, vectorized) -----
__device__ __forceinline__ void unpack8(uint4 u, float* f) {
    const uint32_t* w = &u.x;
#pragma unroll
    for (int i = 0; i < 4; i++) {
        float2 p = __half22float2(*(__half2*)&w[i]);
        f[i * 2] = p.x; f[i * 2 + 1] = p.y;
    }
}
__device__ __forceinline__ uint4 pack8(const float* f) {
    uint4 u;
    uint32_t* w = &u.x;
#pragma unroll
    for (int i = 0; i < 4; i++) {
        __half2 p = __floats2half2_rn(f[i * 2], f[i * 2 + 1]);
        w[i] = *(uint32_t*)&p;
    }
    return u;
}

__global__ __launch_bounds__(256)
void pool_fused(const __half* __restrict__ qkv)
{
    __shared__ float sA[64][192];
    __shared__ float sB[32][192];

    int c  = blockIdx.x;
    int bh = blockIdx.y;
    int b = bh >> 3, h = bh & 7;
    int tid = threadIdx.x;
    size_t poolbase = (size_t)bh * (POOLROWS * 64);

    // Level 1: 512 tasks = 64 li x 8 d-groups (8 halves each), uint4 loads
#pragma unroll
    for (int task = tid; task < 512; task += 256) {
        int li = task >> 3, dg = task & 7;
        size_t base = ((size_t)(b * 4096 + c * 128 + 2 * li)) * QKVW + h * 64 + dg * 8;
        float q0[8], q1[8], k0[8], k1[8], v0[8], v1[8];
        unpack8(*(const uint4*)(qkv + base), q0);
        unpack8(*(const uint4*)(qkv + base + QKVW), q1);
        unpack8(*(const uint4*)(qkv + base + 512), k0);
        unpack8(*(const uint4*)(qkv + base + 512 + QKVW), k1);
        unpack8(*(const uint4*)(qkv + base + 1024), v0);
        unpack8(*(const uint4*)(qkv + base + 1024 + QKVW), v1);
        float qo[8], ko[8], vo[8];
#pragma unroll
        for (int j = 0; j < 8; j++) {
            qo[j] = 0.5f * (q0[j] + q1[j]);
            ko[j] = 0.5f * (k0[j] + k1[j]);
            vo[j] = v0[j] + v1[j];
            sA[li][dg * 8 + j] = qo[j];
            sA[li][64 + dg * 8 + j] = ko[j];
            sA[li][128 + dg * 8 + j] = vo[j];
        }
        size_t dst = poolbase + (size_t)(c * 64 + li) * 64 + dg * 8;
        *(uint4*)(g_poolq + dst) = pack8(qo);
        *(uint4*)(g_poolk + dst) = pack8(ko);
        *(uint4*)(g_poolv + dst) = pack8(vo);
    }
    __syncthreads();

    for (int l = 2; l <= 7; l++) {
        int nl = 64 >> (l - 1);
        int offL = 4096 - (8192 >> l);
        bool srcA = (l & 1) == 0;
        for (int idx = tid; idx < nl * 64; idx += 256) {
            int i = idx >> 6, dd = idx & 63;
            float q0, q1, k0, k1, v0, v1;
            if (srcA) {
                q0 = sA[2 * i][dd];       q1 = sA[2 * i + 1][dd];
                k0 = sA[2 * i][64 + dd];  k1 = sA[2 * i + 1][64 + dd];
                v0 = sA[2 * i][128 + dd]; v1 = sA[2 * i + 1][128 + dd];
            } else {
                q0 = sB[2 * i][dd];       q1 = sB[2 * i + 1][dd];
                k0 = sB[2 * i][64 + dd];  k1 = sB[2 * i + 1][64 + dd];
                v0 = sB[2 * i][128 + dd]; v1 = sB[2 * i + 1][128 + dd];
            }
            float q = 0.5f * (q0 + q1);
            float k = 0.5f * (k0 + k1);
            float v = v0 + v1;
            if (srcA) { sB[i][dd] = q; sB[i][64 + dd] = k; sB[i][128 + dd] = v; }
            else      { sA[i][dd] = q; sA[i][64 + dd] = k; sA[i][128 + dd] = v; }
            size_t dst = poolbase + (size_t)(offL + c * nl + i) * 64 + dd;
            g_poolq[dst] = __float2half_rn(q);
            g_poolk[dst] = __float2half_rn(k);
            g_poolv[dst] = __float2half_rn(v);
        }
        __syncthreads();
    }
}

// ---------------- Shared attention core (per-warp 16x16 block) -------------
struct AttnOut {
    float y[8][4];
    float sr, sr8;
};

__device__ __forceinline__ void attn_block_core(
    const __half* qs, const __half* ks, const __half* vs, int stride,
    char* st, uint32_t su, int lane, AttnOut& o)
{
#pragma unroll
    for (int i = 0; i < 4; i++) {
        int chunk = i * 32 + lane;
        int row = chunk >> 3, qd = chunk & 7;
        uint32_t dst = sw128((uint32_t)(row * 128 + qd * 16));
        *(float4*)(st + dst)        = *(const float4*)(qs + (size_t)row * stride + qd * 8);
        *(float4*)(st + 2048 + dst) = *(const float4*)(ks + (size_t)row * stride + qd * 8);
        *(float4*)(st + 4096 + dst) = *(const float4*)(vs + (size_t)row * stride + qd * 8);
    }
    __syncwarp();

    float s[2][4];
#pragma unroll
    for (int j = 0; j < 2; j++)
#pragma unroll
        for (int t = 0; t < 4; t++) s[j][t] = 0.f;

    int aRow = lane & 15;
    int bRow = (lane & 7) + ((lane & 16) ? 8 : 0);
#pragma unroll
    for (int kk = 0; kk < 4; kk++) {
        uint32_t ah[4], bh[4];
        uint32_t aoff = sw128((uint32_t)(aRow * 128 + (kk * 16 + ((lane & 16) ? 8 : 0)) * 2));
        LDSM_X4(ah[0], ah[1], ah[2], ah[3], su + aoff);
        uint32_t boff = sw128((uint32_t)(bRow * 128 + (kk * 16 + ((lane & 8) ? 8 : 0)) * 2));
        LDSM_X4(bh[0], bh[1], bh[2], bh[3], su + 2048 + boff);
        mma16816h(s[0], ah, &bh[0]);
        mma16816h(s[1], ah, &bh[2]);
    }

    float e[2][4];
    uint32_t aF[4];
#pragma unroll
    for (int j = 0; j < 2; j++) {
#pragma unroll
        for (int t = 0; t < 4; t++) {
            __half hq = __float2half_rn(expf(s[j][t]));
            e[j][t] = __half2float(hq);
        }
        __half2 p0 = __floats2half2_rn(e[j][0], e[j][1]);
        __half2 p1 = __floats2half2_rn(e[j][2], e[j][3]);
        aF[j * 2 + 0] = *(uint32_t*)&p0;
        aF[j * 2 + 1] = *(uint32_t*)&p1;
    }

    float sr  = e[0][0] + e[0][1] + e[1][0] + e[1][1];
    float sr8 = e[0][2] + e[0][3] + e[1][2] + e[1][3];
    sr  += __shfl_xor_sync(0xffffffffu, sr, 1);
    sr  += __shfl_xor_sync(0xffffffffu, sr, 2);
    sr8 += __shfl_xor_sync(0xffffffffu, sr8, 1);
    sr8 += __shfl_xor_sync(0xffffffffu, sr8, 2);
    o.sr = sr; o.sr8 = sr8;

#pragma unroll
    for (int f = 0; f < 8; f++)
#pragma unroll
        for (int t = 0; t < 4; t++) o.y[f][t] = 0.f;

    int vRow = lane & 15;
    int vColBase = (lane & 16) ? 8 : 0;
#pragma unroll
    for (int vi = 0; vi < 4; vi++) {
        uint32_t vb[4];
        uint32_t voff = sw128((uint32_t)(vRow * 128 + (vColBase + vi * 16) * 2));
        LDSM_X4_T(vb[0], vb[1], vb[2], vb[3], su + 4096 + voff);
        mma16816h(o.y[vi * 2 + 0], aF, &vb[0]);
        mma16816h(o.y[vi * 2 + 1], aF, &vb[2]);
    }
}

// ---------------- attn over coarse levels (1..7) ---------------------------
__global__ __launch_bounds__(256)
void attn_coarse()
{
    __shared__ __align__(1024) char smem[8 * 6144];
    int warp = threadIdx.x >> 5;
    int lane = threadIdx.x & 31;
    int wg = blockIdx.x * 8 + warp;            // [0, 8128)

    int bh = wg / 254;
    int r  = wg - bh * 254;
    int level = 1, nb = 128;
    while (r >= nb) { r -= nb; nb >>= 1; level++; }
    int blk = r;
    int kblk = blk ^ 1;

    char* st = smem + warp * 6144;
    const uint32_t su = smem_to_u32(st);

    int off = 4096 - (8192 >> level);
    size_t pb = (size_t)bh * (POOLROWS * 64);
    const __half* qs = g_poolq + pb + (size_t)(off + blk * 16) * 64;
    const __half* ks = g_poolk + pb + (size_t)(off + kblk * 16) * 64;
    const __half* vs = g_poolv + pb + (size_t)(off + blk * 16) * 64;

    AttnOut o;
    attn_block_core(qs, ks, vs, 64, st, su, lane, o);

    int r0 = lane >> 2;
    int c0 = (lane & 3) * 2;
    __half* Ybase = g_Yc + pb + (size_t)(off + blk * 16) * 64;
#pragma unroll
    for (int f = 0; f < 8; f++) {
        int d0 = f * 8 + c0;
        *(__half2*)(Ybase + (size_t)r0 * 64 + d0)       = __floats2half2_rn(o.y[f][0], o.y[f][1]);
        *(__half2*)(Ybase + (size_t)(r0 + 8) * 64 + d0) = __floats2half2_rn(o.y[f][2], o.y[f][3]);
    }
    if ((lane & 3) == 0) {
        float* Ab = g_Ac + (size_t)bh * POOLROWS + off + blk * 16;
        Ab[r0] = o.sr;
        Ab[r0 + 8] = o.sr8;
    }
}

// ---------------- level-0 attention + inline coarse gather + combine -------
__global__ __launch_bounds__(256)
void attn0_combine(const __half* __restrict__ qkv)
{
    __shared__ __align__(1024) char smem[8 * 6144];
    int warp = threadIdx.x >> 5;
    int lane = threadIdx.x & 31;
    int wg = blockIdx.x * 8 + warp;            // [0, 8192)

    int bh = wg >> 8;
    int blk = wg & 255;
    int b = bh >> 3, h = bh & 7;

    char* st = smem + warp * 6144;
    const uint32_t su = smem_to_u32(st);

    size_t rq = (size_t)(b * 4096 + blk * 16) * QKVW;
    const __half* qs = qkv + rq + h * 64;
    const __half* ks = qkv + rq + 512 + h * 64;
    const __half* vs = qkv + rq + 1024 + h * 64;

    AttnOut o;
    attn_block_core(qs, ks, vs, QKVW, st, su, lane, o);

    // ---- gather coarse prefix (levels 1..7) into registers ----
    int n0 = blk * 16;
    int pbase = n0 >> 1;
    size_t pb = (size_t)bh * (POOLROWS * 64);
    const __half* Ycb = g_Yc + pb;
    const float* Acb = g_Ac + (size_t)bh * POOLROWS;

    int gr = lane >> 2;                 // this lane gathers prefix row gr (0..7)
    int gd = (lane & 3) * 16;           // 16 dims starting here
    float gacc[16];
#pragma unroll
    for (int i = 0; i < 16; i++) gacc[i] = 0.f;
    float ac = 0.f;
#pragma unroll
    for (int l = 1; l <= 7; l++) {
        int row = (4096 - (8192 >> l)) + ((pbase + gr) >> (l - 1));
        const __half* src = Ycb + (size_t)row * 64 + gd;
        float fa[8], fb[8];
        unpack8(*(const uint4*)(src), fa);
        unpack8(*(const uint4*)(src + 8), fb);
#pragma unroll
        for (int i = 0; i < 8; i++) { gacc[i] += fa[i]; gacc[8 + i] += fb[i]; }
        ac += Acb[row];
    }

    __syncwarp();                       // all smem reads in core done
    float* ys = (float*)st;             // 8 x 64 fp32 = 2048 B (reuse q region)
#pragma unroll
    for (int i = 0; i < 16; i++) ys[gr * 64 + gd + i] = gacc[i];
    __syncwarp();

    // ---- combine and emit fp16 att ----
    int r0 = lane >> 2;
    int c0 = (lane & 3) * 2;
    int p1 = r0 >> 1;                   // prefix row for output row r0
    int p2 = (r0 + 8) >> 1;             // prefix row for output row r0+8
    float acA = __shfl_sync(0xffffffffu, ac, p1 * 4);
    float acB = __shfl_sync(0xffffffffu, ac, p2 * 4);
    float invA_r  = 1.f / (o.sr  + acA + 1e-8f);
    float invA_r8 = 1.f / (o.sr8 + acB + 1e-8f);

    __half* att_r  = g_atth + (size_t)(b * 4096 + n0 + r0) * 512 + h * 64;
    __half* att_r8 = g_atth + (size_t)(b * 4096 + n0 + r0 + 8) * 512 + h * 64;
#pragma unroll
    for (int f = 0; f < 8; f++) {
        int d0 = f * 8 + c0;
        float2 c_r  = *(float2*)&ys[p1 * 64 + d0];
        float2 c_r8 = *(float2*)&ys[p2 * 64 + d0];
        *(__half2*)(att_r + d0)  = __floats2half2_rn((o.y[f][0] + c_r.x) * invA_r,
                                                     (o.y[f][1] + c_r.y) * invA_r);
        *(__half2*)(att_r8 + d0) = __floats2half2_rn((o.y[f][2] + c_r8.x) * invA_r8,
                                                     (o.y[f][3] + c_r8.y) * invA_r8);
    }
}

// ---------------- Launch ----------------
extern "C" void kernel_launch(void* const* d_in, const int* in_sizes, int n_in,
                              void* d_out, int out_size)
{
    const float* x     = (const float*)d_in[0];
    const float* w_qkv = (const float*)d_in[1];
    const float* w_out = (const float*)d_in[2];
    const float* b_out = (const float*)d_in[3];
    float* out = (float*)d_out;

    __half *xh, *wqh, *woh, *ath, *qkv16;
    cudaGetSymbolAddress((void**)&xh, g_xh);
    cudaGetSymbolAddress((void**)&wqh, g_wqh);
    cudaGetSymbolAddress((void**)&woh, g_woh);
    cudaGetSymbolAddress((void**)&ath, g_atth);
    cudaGetSymbolAddress((void**)&qkv16, g_qkv16);

    cudaFuncSetAttribute(gemm_fp16<0>, cudaFuncAttributeMaxDynamicSharedMemorySize, GS_SMEM);
    cudaFuncSetAttribute(gemm_fp16<1>, cudaFuncAttributeMaxDynamicSharedMemorySize, GS_SMEM);

    // 1) Convert inputs to fp16
    convert_all<<<18432, 256>>>(x, w_qkv, w_out);

    // 2) QKV projection -> fp16 qkv (q pre-scaled 0.125)
    gemm_fp16<1><<<dim3(QKVW / 128, NROWS / 128), 256, GS_SMEM>>>(
        xh, wqh, nullptr, nullptr, qkv16, NROWS, QKVW, 1024);

    // 3) Fused pooling (fp16 planes, vectorized)
    pool_fused<<<dim3(32, 32), 256>>>(qkv16);

    // 4) Coarse attention (levels 1..7)
    attn_coarse<<<1016, 256>>>();

    // 5) Level-0 attention + inline coarse gather + combine -> fp16 att
    attn0_combine<<<1024, 256>>>(qkv16);

    // 6) Output projection (fp32 out + bias)
    gemm_fp16<0><<<dim3(1024 / 128, NROWS / 128), 256, GS_SMEM>>>(
        ath, woh, b_out, out, nullptr, NROWS, 1024, 512);
}